// round 3
// baseline (speedup 1.0000x reference)
#include <cuda_runtime.h>
#include <math.h>

// ---------------- problem constants ----------------
constexpr int Bc   = 2;
constexpr int Sc   = 2048;
constexpr int HIDc = 2048;
constexpr int NHc  = 16;
constexpr int HDc  = 128;
constexpr int RDc  = 32;
constexpr int SBc  = 204;           // int(0.1 * S)
constexpr int RBc  = 204;           // int(0.1 * S)
constexpr int MBc  = 128;           // MERGE_BUDGET
constexpr int TKc  = 16;            // TOPK
constexpr int NCAND = Sc - RBc - SBc;   // 1640 candidates in [SB, S-RB)

// ---------------- device scratch (static, allocation-free) ----------------
__device__ float g_qkv [(size_t)Bc * Sc * 3 * HIDc];     //  96 MB  (B,S, NH*3*HD)
__device__ float g_q   [(size_t)Bc * NHc * Sc * HDc];    //  32 MB
__device__ float g_k   [(size_t)Bc * NHc * Sc * HDc];    //  32 MB
__device__ float g_v   [(size_t)Bc * NHc * Sc * HDc];    //  32 MB
__device__ float g_attn[(size_t)Bc * NHc * Sc * Sc];     // 512 MB
__device__ float g_outh[(size_t)Bc * Sc * HIDc];         //  32 MB  (B,S,HID) head-merged
__device__ float g_colsum[NHc * Sc];
__device__ float g_ratio [NHc * Sc];
__device__ int   g_topidx[NHc * TKc];
__device__ float g_topval[NHc * TKc];

// ---------------- generic TN SGEMM: C[M,N] = A[M,K] * B[N,K]^T + bias ----------------
// M, N multiples of 128; K multiple of 8.
__global__ __launch_bounds__(256) void gemm_tn(
    const float* __restrict__ A, const float* __restrict__ Bm,
    const float* __restrict__ bias, float* __restrict__ C,
    int M, int N, int K)
{
    constexpr int BK = 8;
    __shared__ __align__(16) float As[BK][128];
    __shared__ __align__(16) float Bs[BK][128];

    const int tid = threadIdx.x;
    const int bm  = blockIdx.y * 128;
    const int bn  = blockIdx.x * 128;
    const int ty  = tid >> 4, tx = tid & 15;
    const int lr  = tid >> 1, lc = (tid & 1) * 4;

    const float* Ap = A  + (size_t)(bm + lr) * K + lc;
    const float* Bp = Bm + (size_t)(bn + lr) * K + lc;

    float acc[8][8];
#pragma unroll
    for (int i = 0; i < 8; i++)
#pragma unroll
        for (int j = 0; j < 8; j++) acc[i][j] = 0.f;

    for (int k0 = 0; k0 < K; k0 += BK) {
        float4 a4 = *(const float4*)(Ap + k0);
        float4 b4 = *(const float4*)(Bp + k0);
        As[lc + 0][lr] = a4.x; As[lc + 1][lr] = a4.y;
        As[lc + 2][lr] = a4.z; As[lc + 3][lr] = a4.w;
        Bs[lc + 0][lr] = b4.x; Bs[lc + 1][lr] = b4.y;
        Bs[lc + 2][lr] = b4.z; Bs[lc + 3][lr] = b4.w;
        __syncthreads();
#pragma unroll
        for (int kk = 0; kk < BK; kk++) {
            float4 a0 = *(const float4*)&As[kk][ty * 8];
            float4 a1 = *(const float4*)&As[kk][ty * 8 + 4];
            float4 b0 = *(const float4*)&Bs[kk][tx * 8];
            float4 b1 = *(const float4*)&Bs[kk][tx * 8 + 4];
            float ra[8] = {a0.x, a0.y, a0.z, a0.w, a1.x, a1.y, a1.z, a1.w};
            float rb[8] = {b0.x, b0.y, b0.z, b0.w, b1.x, b1.y, b1.z, b1.w};
#pragma unroll
            for (int i = 0; i < 8; i++)
#pragma unroll
                for (int j = 0; j < 8; j++) acc[i][j] += ra[i] * rb[j];
        }
        __syncthreads();
    }

    float bl[8];
#pragma unroll
    for (int j = 0; j < 8; j++) bl[j] = bias ? bias[bn + tx * 8 + j] : 0.f;
#pragma unroll
    for (int i = 0; i < 8; i++) {
        float* cp = C + (size_t)(bm + ty * 8 + i) * N + bn + tx * 8;
        *(float4*)cp =
            make_float4(acc[i][0] + bl[0], acc[i][1] + bl[1], acc[i][2] + bl[2], acc[i][3] + bl[3]);
        *(float4*)(cp + 4) =
            make_float4(acc[i][4] + bl[4], acc[i][5] + bl[5], acc[i][6] + bl[6], acc[i][7] + bl[7]);
    }
}

// ---------------- RoPE + scatter qkv -> Q/K/V in (B,NH,S,HD) ----------------
__global__ void rope_scatter(const int* __restrict__ pos)
{
    const int s = blockIdx.x, h = blockIdx.y, b = blockIdx.z, d = threadIdx.x;
    const size_t base = ((size_t)(b * Sc + s)) * (3 * HIDc) + (size_t)h * (3 * HDc);

    float qv = g_qkv[base + d];
    float kv = g_qkv[base + HDc + d];
    float vv = g_qkv[base + 2 * HDc + d];

    if (d < RDc) {
        const int i = d & 15;
        const float invf = exp2f(-((float)i * (1.0f / 16.0f)) * 13.28771237954945f); // log2(10000)
        const float t = (float)pos[b * Sc + s];
        const float ang = t * invf;
        float sn, c;
        sincosf(ang, &sn, &c);
        if (d < 16) {
            qv = qv * c - g_qkv[base + d + 16] * sn;
            kv = kv * c - g_qkv[base + HDc + d + 16] * sn;
        } else {
            qv = qv * c + g_qkv[base + d - 16] * sn;
            kv = kv * c + g_qkv[base + HDc + d - 16] * sn;
        }
    }
    const size_t o = ((size_t)((b * NHc + h) * Sc) + s) * HDc + d;
    g_q[o] = qv; g_k[o] = kv; g_v[o] = vv;
}

// ---------------- scores = scale * Q K^T (batched per b,h; upper blocks skipped) ----------------
__global__ __launch_bounds__(256) void scores_kernel()
{
    if (blockIdx.x > blockIdx.y) return;   // tile entirely above the diagonal
    constexpr int BK = 8;
    constexpr float SCALE = 0.08838834764831845f;  // 1/sqrt(128)
    __shared__ __align__(16) float Qs[BK][128];
    __shared__ __align__(16) float Ks[BK][128];

    const int bh = blockIdx.z;
    const float* A  = g_q + (size_t)bh * Sc * HDc;
    const float* Bm = g_k + (size_t)bh * Sc * HDc;
    float* C = g_attn + (size_t)bh * Sc * Sc;

    const int tid = threadIdx.x;
    const int bm = blockIdx.y * 128, bn = blockIdx.x * 128;
    const int ty = tid >> 4, tx = tid & 15;
    const int lr = tid >> 1, lc = (tid & 1) * 4;

    const float* Ap = A  + (size_t)(bm + lr) * HDc + lc;
    const float* Bp = Bm + (size_t)(bn + lr) * HDc + lc;

    float acc[8][8];
#pragma unroll
    for (int i = 0; i < 8; i++)
#pragma unroll
        for (int j = 0; j < 8; j++) acc[i][j] = 0.f;

    for (int k0 = 0; k0 < HDc; k0 += BK) {
        float4 a4 = *(const float4*)(Ap + k0);
        float4 b4 = *(const float4*)(Bp + k0);
        Qs[lc + 0][lr] = a4.x; Qs[lc + 1][lr] = a4.y;
        Qs[lc + 2][lr] = a4.z; Qs[lc + 3][lr] = a4.w;
        Ks[lc + 0][lr] = b4.x; Ks[lc + 1][lr] = b4.y;
        Ks[lc + 2][lr] = b4.z; Ks[lc + 3][lr] = b4.w;
        __syncthreads();
#pragma unroll
        for (int kk = 0; kk < BK; kk++) {
            float4 a0 = *(const float4*)&Qs[kk][ty * 8];
            float4 a1 = *(const float4*)&Qs[kk][ty * 8 + 4];
            float4 b0 = *(const float4*)&Ks[kk][tx * 8];
            float4 b1 = *(const float4*)&Ks[kk][tx * 8 + 4];
            float ra[8] = {a0.x, a0.y, a0.z, a0.w, a1.x, a1.y, a1.z, a1.w};
            float rb[8] = {b0.x, b0.y, b0.z, b0.w, b1.x, b1.y, b1.z, b1.w};
#pragma unroll
            for (int i = 0; i < 8; i++)
#pragma unroll
                for (int j = 0; j < 8; j++) acc[i][j] += ra[i] * rb[j];
        }
        __syncthreads();
    }
#pragma unroll
    for (int i = 0; i < 8; i++) {
        float* cp = C + (size_t)(bm + ty * 8 + i) * Sc + bn + tx * 8;
        *(float4*)cp = make_float4(acc[i][0] * SCALE, acc[i][1] * SCALE,
                                   acc[i][2] * SCALE, acc[i][3] * SCALE);
        *(float4*)(cp + 4) = make_float4(acc[i][4] * SCALE, acc[i][5] * SCALE,
                                         acc[i][6] * SCALE, acc[i][7] * SCALE);
    }
}

// ---------------- causal row softmax (adds attention_mask), in place ----------------
__global__ __launch_bounds__(256) void softmax_kernel(const float* __restrict__ amask)
{
    const int row = blockIdx.x;            // b*NH*S + h*S + q
    const int q  = row & (Sc - 1);
    const int bh = row >> 11;              // / 2048
    const int b  = bh / NHc;
    float* ap = g_attn + (size_t)row * Sc;
    const float* mp = amask + (size_t)b * Sc;

    __shared__ float sv[Sc];
    __shared__ float red[256];
    const int tid = threadIdx.x;
    const int n = q + 1;

    float lm = -3.4e38f;
    for (int k = tid; k < n; k += 256) {
        float v = ap[k] + mp[k];
        sv[k] = v;
        lm = fmaxf(lm, v);
    }
    red[tid] = lm; __syncthreads();
    for (int st = 128; st > 0; st >>= 1) {
        if (tid < st) red[tid] = fmaxf(red[tid], red[tid + st]);
        __syncthreads();
    }
    const float m = red[0];
    __syncthreads();

    float ls = 0.f;
    for (int k = tid; k < n; k += 256) {
        float e = __expf(sv[k] - m);
        sv[k] = e;
        ls += e;
    }
    red[tid] = ls; __syncthreads();
    for (int st = 128; st > 0; st >>= 1) {
        if (tid < st) red[tid] += red[tid + st];
        __syncthreads();
    }
    const float inv = 1.0f / red[0];
    for (int k = tid; k < n; k += 256) ap[k] = sv[k] * inv;
}

// ---------------- column sums over q (and last-MB q window), summed over b; deterministic ----------------
__global__ void colreduce_kernel()
{
    const int k = blockIdx.x * 256 + threadIdx.x;
    const int h = blockIdx.y;
    const int q0 = blockIdx.x * 256;       // min column in this block -> safe start
    float s = 0.f, r = 0.f;
    for (int b = 0; b < Bc; b++) {
        const float* ap = g_attn + ((size_t)(b * NHc + h)) * Sc * Sc;
        for (int q = q0; q < Sc; q++) {
            if (q >= k) {
                float a = ap[(size_t)q * Sc + k];
                s += a;
                if (q >= Sc - MBc) r += a;
            }
        }
    }
    g_colsum[h * Sc + k] = s;
    g_ratio [h * Sc + k] = r;
}

// ---------------- top-k per head (candidates [SB, S-RB); jax tie-break: lowest index) ----------------
__global__ __launch_bounds__(256) void topk_kernel()
{
    const int h = blockIdx.x, tid = threadIdx.x;
    __shared__ float tv[NCAND];
    __shared__ float rv[256];
    __shared__ int   ri[256];

    for (int i = tid; i < NCAND; i += 256) tv[i] = g_colsum[h * Sc + SBc + i];
    __syncthreads();

    for (int r = 0; r < TKc; r++) {
        float bv = -1e30f; int bi = NCAND;
        for (int i = tid; i < NCAND; i += 256) {
            float v = tv[i];
            if (v > bv) { bv = v; bi = i; }   // strided scan -> lowest index per thread on ties
        }
        rv[tid] = bv; ri[tid] = bi;
        __syncthreads();
        for (int st = 128; st > 0; st >>= 1) {
            if (tid < st) {
                if (rv[tid + st] > rv[tid] ||
                    (rv[tid + st] == rv[tid] && ri[tid + st] < ri[tid])) {
                    rv[tid] = rv[tid + st]; ri[tid] = ri[tid + st];
                }
            }
            __syncthreads();
        }
        if (tid == 0) {
            const int gi = ri[0] + SBc;
            g_topidx[h * TKc + r] = gi;
            g_topval[h * TKc + r] = g_ratio[h * Sc + gi] * (1.0f / MBc);
            tv[ri[0]] = -1e30f;
        }
        __syncthreads();
    }
}

// ---------------- v[b,h,SB,:] = sum_j v[b,h,idx_j,:] * val_j ----------------
__global__ void vupdate_kernel()
{
    const int bh = blockIdx.x;
    const int h  = bh % NHc;
    const int d  = threadIdx.x;
    float* vp = g_v + (size_t)bh * Sc * HDc;
    float acc = 0.f;
#pragma unroll
    for (int j = 0; j < TKc; j++)
        acc += vp[(size_t)g_topidx[h * TKc + j] * HDc + d] * g_topval[h * TKc + j];
    vp[(size_t)SBc * HDc + d] = acc;   // same thread reads then writes its own lane: no hazard
}

// ---------------- out = attn @ v (causal), scatter to (B,S,HID) ----------------
__global__ __launch_bounds__(256) void attnv_kernel()
{
    constexpr int BK = 16;
    __shared__ __align__(16) float As[BK][128];
    __shared__ __align__(16) float Vs[BK][HDc];

    const int tid = threadIdx.x;
    const int bh  = blockIdx.z;
    const int bm  = blockIdx.x * 128;
    const float* attn = g_attn + (size_t)bh * Sc * Sc;
    const float* vp   = g_v    + (size_t)bh * Sc * HDc;

    const int ty = tid >> 4, tx = tid & 15;
    const int lr = tid >> 1, lc8 = (tid & 1) * 8;
    const int vr = tid >> 4, vc = (tid & 15) * 8;

    float acc[8][8];
#pragma unroll
    for (int i = 0; i < 8; i++)
#pragma unroll
        for (int j = 0; j < 8; j++) acc[i][j] = 0.f;

    const int q_l = bm + lr;
    const float* arow = attn + (size_t)q_l * Sc;
    const int ktiles = (bm + 128) / BK;

    for (int kt = 0; kt < ktiles; kt++) {
        const int k0 = kt * BK;
        float4 a0 = *(const float4*)(arow + k0 + lc8);
        float4 a1 = *(const float4*)(arow + k0 + lc8 + 4);
        const int kb = k0 + lc8;
        As[lc8 + 0][lr] = (kb + 0 <= q_l) ? a0.x : 0.f;
        As[lc8 + 1][lr] = (kb + 1 <= q_l) ? a0.y : 0.f;
        As[lc8 + 2][lr] = (kb + 2 <= q_l) ? a0.z : 0.f;
        As[lc8 + 3][lr] = (kb + 3 <= q_l) ? a0.w : 0.f;
        As[lc8 + 4][lr] = (kb + 4 <= q_l) ? a1.x : 0.f;
        As[lc8 + 5][lr] = (kb + 5 <= q_l) ? a1.y : 0.f;
        As[lc8 + 6][lr] = (kb + 6 <= q_l) ? a1.z : 0.f;
        As[lc8 + 7][lr] = (kb + 7 <= q_l) ? a1.w : 0.f;

        float4 v0 = *(const float4*)(vp + (size_t)(k0 + vr) * HDc + vc);
        float4 v1 = *(const float4*)(vp + (size_t)(k0 + vr) * HDc + vc + 4);
        *(float4*)&Vs[vr][vc]     = v0;
        *(float4*)&Vs[vr][vc + 4] = v1;
        __syncthreads();
#pragma unroll
        for (int kk = 0; kk < BK; kk++) {
            float4 ra0 = *(const float4*)&As[kk][ty * 8];
            float4 ra1 = *(const float4*)&As[kk][ty * 8 + 4];
            float4 rb0 = *(const float4*)&Vs[kk][tx * 8];
            float4 rb1 = *(const float4*)&Vs[kk][tx * 8 + 4];
            float ra[8] = {ra0.x, ra0.y, ra0.z, ra0.w, ra1.x, ra1.y, ra1.z, ra1.w};
            float rb[8] = {rb0.x, rb0.y, rb0.z, rb0.w, rb1.x, rb1.y, rb1.z, rb1.w};
#pragma unroll
            for (int i = 0; i < 8; i++)
#pragma unroll
                for (int j = 0; j < 8; j++) acc[i][j] += ra[i] * rb[j];
        }
        __syncthreads();
    }

    const int b = bh / NHc, h = bh % NHc;
#pragma unroll
    for (int i = 0; i < 8; i++) {
        const int q = bm + ty * 8 + i;
        float* op = g_outh + ((size_t)(b * Sc + q)) * HIDc + h * HDc + tx * 8;
        *(float4*)op       = make_float4(acc[i][0], acc[i][1], acc[i][2], acc[i][3]);
        *(float4*)(op + 4) = make_float4(acc[i][4], acc[i][5], acc[i][6], acc[i][7]);
    }
}

// ---------------- launch ----------------
extern "C" void kernel_launch(void* const* d_in, const int* in_sizes, int n_in,
                              void* d_out, int out_size)
{
    (void)in_sizes; (void)n_in; (void)out_size;
    const float* hs    = (const float*)d_in[0];   // hidden_states (B,S,HID)
    const float* amask = (const float*)d_in[1];   // attention_mask (B,1,1,S)
    const int*   pos   = (const int*)  d_in[2];   // position_ids (B,S)
    const float* Wqkv  = (const float*)d_in[3];   // (3*HID, HID)
    const float* bqkv  = (const float*)d_in[4];   // (3*HID,)
    const float* Wd    = (const float*)d_in[5];   // (HID, HID)
    const float* bd    = (const float*)d_in[6];   // (HID,)
    float* out = (float*)d_out;

    void *p_qkv = nullptr, *p_outh = nullptr;
    cudaGetSymbolAddress(&p_qkv, g_qkv);
    cudaGetSymbolAddress(&p_outh, g_outh);

    // 1. QKV projection: (B*S, 3*HID)
    gemm_tn<<<dim3(3 * HIDc / 128, (Bc * Sc) / 128), 256>>>(
        hs, Wqkv, bqkv, (float*)p_qkv, Bc * Sc, 3 * HIDc, HIDc);

    // 2. RoPE + scatter to (B,NH,S,HD)
    rope_scatter<<<dim3(Sc, NHc, Bc), HDc>>>(pos);

    // 3. scaled QK^T (causal tiles only)
    scores_kernel<<<dim3(Sc / 128, Sc / 128, Bc * NHc), 256>>>();

    // 4. row softmax (+attention_mask)
    softmax_kernel<<<Bc * NHc * Sc, 256>>>(amask);

    // 5. column statistics (attn_score, ratio), deterministic
    colreduce_kernel<<<dim3(Sc / 256, NHc), 256>>>();

    // 6. per-head top-16
    topk_kernel<<<NHc, 256>>>();

    // 7. merged row write into v[:, :, SB, :]
    vupdate_kernel<<<Bc * NHc, HDc>>>();

    // 8. out = attn @ v, scattered to (B,S,HID)
    attnv_kernel<<<dim3(Sc / 128, 1, Bc * NHc), 256>>>();

    // 9. dense projection to d_out
    gemm_tn<<<dim3(HIDc / 128, (Bc * Sc) / 128), 256>>>(
        (const float*)p_outh, Wd, bd, out, Bc * Sc, HIDc, HIDc);
}

// round 7
// speedup vs baseline: 1.4097x; 1.4097x over previous
#include <cuda_runtime.h>
#include <math.h>

// ---------------- problem constants ----------------
constexpr int Bc   = 2;
constexpr int Sc   = 2048;
constexpr int HIDc = 2048;
constexpr int NHc  = 16;
constexpr int HDc  = 128;
constexpr int RDc  = 32;
constexpr int SBc  = 204;           // int(0.1 * S)
constexpr int RBc  = 204;           // int(0.1 * S)
constexpr int MBc  = 128;           // MERGE_BUDGET
constexpr int TKc  = 16;            // TOPK
constexpr int NCAND = Sc - RBc - SBc;   // 1640 candidates in [SB, S-RB)

// ---------------- device scratch (static, allocation-free) ----------------
__device__ float g_qkv [(size_t)Bc * Sc * 3 * HIDc];     //  96 MB
__device__ float g_q   [(size_t)Bc * NHc * Sc * HDc];    //  32 MB
__device__ float g_k   [(size_t)Bc * NHc * Sc * HDc];    //  32 MB
__device__ float g_v   [(size_t)Bc * NHc * Sc * HDc];    //  32 MB
__device__ float g_attn[(size_t)Bc * NHc * Sc * Sc];     // 512 MB
__device__ float g_outh[(size_t)Bc * Sc * HIDc];         //  32 MB
__device__ float g_colsum[NHc * Sc];
__device__ float g_ratio [NHc * Sc];
__device__ int   g_topidx[NHc * TKc];
__device__ float g_topval[NHc * TKc];

// ---------------- tf32 helpers ----------------
__device__ __forceinline__ unsigned f2t(float x) {
    unsigned r; asm("cvt.rna.tf32.f32 %0, %1;" : "=r"(r) : "f"(x)); return r;
}
__device__ __forceinline__ void mma8(float* c, const unsigned* a, const unsigned* b) {
    asm volatile(
        "mma.sync.aligned.m16n8k8.row.col.f32.tf32.tf32.f32 "
        "{%0,%1,%2,%3}, {%4,%5,%6,%7}, {%8,%9}, {%0,%1,%2,%3};"
        : "+f"(c[0]), "+f"(c[1]), "+f"(c[2]), "+f"(c[3])
        : "r"(a[0]), "r"(a[1]), "r"(a[2]), "r"(a[3]), "r"(b[0]), "r"(b[1]));
}

// ================= TF32 TN GEMM: C[M,N] = A[M,K] * B[N,K]^T + bias =================
// block 128x128, BK=16, 256 threads (8 warps: 2m x 4n, warp tile 64x32)
__global__ __launch_bounds__(256) void gemm_tn_tc(
    const float* __restrict__ A, const float* __restrict__ Bm,
    const float* __restrict__ bias, float* __restrict__ C,
    int M, int N, int K)
{
    __shared__ unsigned As[16][132];
    __shared__ unsigned Bs[16][132];

    const int tid = threadIdx.x, lane = tid & 31, w = tid >> 5;
    const int bm = blockIdx.y * 128, bn = blockIdx.x * 128;
    const int wm = (w >> 2) * 64, wn = (w & 3) * 32;
    const int lrow = tid & 127, lkh = (tid >> 7) * 8;

    const float* Ap = A  + (size_t)(bm + lrow) * K + lkh;
    const float* Bp = Bm + (size_t)(bn + lrow) * K + lkh;

    float acc[4][4][4];
#pragma unroll
    for (int mt = 0; mt < 4; mt++)
#pragma unroll
        for (int nt = 0; nt < 4; nt++)
#pragma unroll
            for (int i = 0; i < 4; i++) acc[mt][nt][i] = 0.f;

    float4 pa0 = *(const float4*)Ap,       pa1 = *(const float4*)(Ap + 4);
    float4 pb0 = *(const float4*)Bp,       pb1 = *(const float4*)(Bp + 4);

    const int ar = lane >> 2, ak = lane & 3;

    for (int k0 = 0; k0 < K; k0 += 16) {
        As[lkh + 0][lrow] = f2t(pa0.x); As[lkh + 1][lrow] = f2t(pa0.y);
        As[lkh + 2][lrow] = f2t(pa0.z); As[lkh + 3][lrow] = f2t(pa0.w);
        As[lkh + 4][lrow] = f2t(pa1.x); As[lkh + 5][lrow] = f2t(pa1.y);
        As[lkh + 6][lrow] = f2t(pa1.z); As[lkh + 7][lrow] = f2t(pa1.w);
        Bs[lkh + 0][lrow] = f2t(pb0.x); Bs[lkh + 1][lrow] = f2t(pb0.y);
        Bs[lkh + 2][lrow] = f2t(pb0.z); Bs[lkh + 3][lrow] = f2t(pb0.w);
        Bs[lkh + 4][lrow] = f2t(pb1.x); Bs[lkh + 5][lrow] = f2t(pb1.y);
        Bs[lkh + 6][lrow] = f2t(pb1.z); Bs[lkh + 7][lrow] = f2t(pb1.w);
        __syncthreads();

        const int kn = (k0 + 16 < K) ? (k0 + 16) : 0;   // harmless reload on last iter
        pa0 = *(const float4*)(Ap + kn); pa1 = *(const float4*)(Ap + kn + 4);
        pb0 = *(const float4*)(Bp + kn); pb1 = *(const float4*)(Bp + kn + 4);

#pragma unroll
        for (int ks = 0; ks < 16; ks += 8) {
            unsigned a[4][4], b[4][2];
#pragma unroll
            for (int mt = 0; mt < 4; mt++) {
                const int m0 = wm + mt * 16 + ar;
                a[mt][0] = As[ks + ak][m0];
                a[mt][1] = As[ks + ak][m0 + 8];
                a[mt][2] = As[ks + 4 + ak][m0];
                a[mt][3] = As[ks + 4 + ak][m0 + 8];
            }
#pragma unroll
            for (int nt = 0; nt < 4; nt++) {
                const int n0 = wn + nt * 8 + ar;
                b[nt][0] = Bs[ks + ak][n0];
                b[nt][1] = Bs[ks + 4 + ak][n0];
            }
#pragma unroll
            for (int mt = 0; mt < 4; mt++)
#pragma unroll
                for (int nt = 0; nt < 4; nt++) mma8(acc[mt][nt], a[mt], b[nt]);
        }
        __syncthreads();
    }

    const int ac2 = (lane & 3) * 2;
#pragma unroll
    for (int nt = 0; nt < 4; nt++) {
        const int col = bn + wn + nt * 8 + ac2;
        float b0 = 0.f, b1 = 0.f;
        if (bias) { b0 = bias[col]; b1 = bias[col + 1]; }
#pragma unroll
        for (int mt = 0; mt < 4; mt++) {
            const int r0 = bm + wm + mt * 16 + ar;
            *(float2*)&C[(size_t)r0 * N + col] =
                make_float2(acc[mt][nt][0] + b0, acc[mt][nt][1] + b1);
            *(float2*)&C[(size_t)(r0 + 8) * N + col] =
                make_float2(acc[mt][nt][2] + b0, acc[mt][nt][3] + b1);
        }
    }
}

// ================= scores = scale * Q K^T (TF32, causal tiles only) =================
__global__ __launch_bounds__(256) void scores_tc()
{
    if (blockIdx.x > blockIdx.y) return;
    constexpr float SCALE = 0.08838834764831845f;  // 1/sqrt(128)
    __shared__ unsigned As[16][132];
    __shared__ unsigned Bs[16][132];

    const int tid = threadIdx.x, lane = tid & 31, w = tid >> 5;
    const int bh = blockIdx.z;
    const int bm = blockIdx.y * 128, bn = blockIdx.x * 128;
    const int wm = (w >> 2) * 64, wn = (w & 3) * 32;
    const int lrow = tid & 127, lkh = (tid >> 7) * 8;

    const float* Ap = g_q + (size_t)bh * Sc * HDc + (size_t)(bm + lrow) * HDc + lkh;
    const float* Bp = g_k + (size_t)bh * Sc * HDc + (size_t)(bn + lrow) * HDc + lkh;
    float* C = g_attn + (size_t)bh * Sc * Sc;

    float acc[4][4][4];
#pragma unroll
    for (int mt = 0; mt < 4; mt++)
#pragma unroll
        for (int nt = 0; nt < 4; nt++)
#pragma unroll
            for (int i = 0; i < 4; i++) acc[mt][nt][i] = 0.f;

    float4 pa0 = *(const float4*)Ap, pa1 = *(const float4*)(Ap + 4);
    float4 pb0 = *(const float4*)Bp, pb1 = *(const float4*)(Bp + 4);
    const int ar = lane >> 2, ak = lane & 3;

    for (int k0 = 0; k0 < HDc; k0 += 16) {
        As[lkh + 0][lrow] = f2t(pa0.x); As[lkh + 1][lrow] = f2t(pa0.y);
        As[lkh + 2][lrow] = f2t(pa0.z); As[lkh + 3][lrow] = f2t(pa0.w);
        As[lkh + 4][lrow] = f2t(pa1.x); As[lkh + 5][lrow] = f2t(pa1.y);
        As[lkh + 6][lrow] = f2t(pa1.z); As[lkh + 7][lrow] = f2t(pa1.w);
        Bs[lkh + 0][lrow] = f2t(pb0.x); Bs[lkh + 1][lrow] = f2t(pb0.y);
        Bs[lkh + 2][lrow] = f2t(pb0.z); Bs[lkh + 3][lrow] = f2t(pb0.w);
        Bs[lkh + 4][lrow] = f2t(pb1.x); Bs[lkh + 5][lrow] = f2t(pb1.y);
        Bs[lkh + 6][lrow] = f2t(pb1.z); Bs[lkh + 7][lrow] = f2t(pb1.w);
        __syncthreads();

        const int kn = (k0 + 16 < HDc) ? (k0 + 16) : 0;
        pa0 = *(const float4*)(Ap + kn); pa1 = *(const float4*)(Ap + kn + 4);
        pb0 = *(const float4*)(Bp + kn); pb1 = *(const float4*)(Bp + kn + 4);

#pragma unroll
        for (int ks = 0; ks < 16; ks += 8) {
            unsigned a[4][4], b[4][2];
#pragma unroll
            for (int mt = 0; mt < 4; mt++) {
                const int m0 = wm + mt * 16 + ar;
                a[mt][0] = As[ks + ak][m0];
                a[mt][1] = As[ks + ak][m0 + 8];
                a[mt][2] = As[ks + 4 + ak][m0];
                a[mt][3] = As[ks + 4 + ak][m0 + 8];
            }
#pragma unroll
            for (int nt = 0; nt < 4; nt++) {
                const int n0 = wn + nt * 8 + ar;
                b[nt][0] = Bs[ks + ak][n0];
                b[nt][1] = Bs[ks + 4 + ak][n0];
            }
#pragma unroll
            for (int mt = 0; mt < 4; mt++)
#pragma unroll
                for (int nt = 0; nt < 4; nt++) mma8(acc[mt][nt], a[mt], b[nt]);
        }
        __syncthreads();
    }

    const int ac2 = (lane & 3) * 2;
#pragma unroll
    for (int nt = 0; nt < 4; nt++) {
        const int col = bn + wn + nt * 8 + ac2;
#pragma unroll
        for (int mt = 0; mt < 4; mt++) {
            const int r0 = bm + wm + mt * 16 + ar;
            *(float2*)&C[(size_t)r0 * Sc + col] =
                make_float2(acc[mt][nt][0] * SCALE, acc[mt][nt][1] * SCALE);
            *(float2*)&C[(size_t)(r0 + 8) * Sc + col] =
                make_float2(acc[mt][nt][2] * SCALE, acc[mt][nt][3] * SCALE);
        }
    }
}

// ================= out = attn @ v (TF32, causal), scatter to (B,S,HID) =================
__global__ __launch_bounds__(256) void attnv_tc()
{
    __shared__ unsigned As[16][132];   // [k][m]
    __shared__ unsigned Vs[128][20];   // [n][k] (pad 20 -> conflict-free frag reads)

    const int tid = threadIdx.x, lane = tid & 31, w = tid >> 5;
    const int bh = blockIdx.y;
    const int bm = blockIdx.x * 128;
    const int wm = (w >> 2) * 64, wn = (w & 3) * 32;

    const float* attn = g_attn + (size_t)bh * Sc * Sc;
    const float* vp   = g_v    + (size_t)bh * Sc * HDc;

    const int lrow = tid & 127, lkh = (tid >> 7) * 8;
    const int q_l = bm + lrow;
    const float* arow = attn + (size_t)q_l * Sc;
    const int vk = tid & 15, vn = (tid >> 4) * 8;

    float acc[4][4][4];
#pragma unroll
    for (int mt = 0; mt < 4; mt++)
#pragma unroll
        for (int nt = 0; nt < 4; nt++)
#pragma unroll
            for (int i = 0; i < 4; i++) acc[mt][nt][i] = 0.f;

    const int ar = lane >> 2, ak = lane & 3;
    const int kend = bm + 128;

    for (int k0 = 0; k0 < kend; k0 += 16) {
        // A tile with per-element causal mask (entries k > q are garbage in memory)
        float4 a0v = *(const float4*)(arow + k0 + lkh);
        float4 a1v = *(const float4*)(arow + k0 + lkh + 4);
        const int kb = k0 + lkh;
        As[lkh + 0][lrow] = (kb + 0 <= q_l) ? f2t(a0v.x) : 0u;
        As[lkh + 1][lrow] = (kb + 1 <= q_l) ? f2t(a0v.y) : 0u;
        As[lkh + 2][lrow] = (kb + 2 <= q_l) ? f2t(a0v.z) : 0u;
        As[lkh + 3][lrow] = (kb + 3 <= q_l) ? f2t(a0v.w) : 0u;
        As[lkh + 4][lrow] = (kb + 4 <= q_l) ? f2t(a1v.x) : 0u;
        As[lkh + 5][lrow] = (kb + 5 <= q_l) ? f2t(a1v.y) : 0u;
        As[lkh + 6][lrow] = (kb + 6 <= q_l) ? f2t(a1v.z) : 0u;
        As[lkh + 7][lrow] = (kb + 7 <= q_l) ? f2t(a1v.w) : 0u;

        // V tile: Vs[n][k] = v[k0+k][n]
        const float* vr = vp + (size_t)(k0 + vk) * HDc + vn;
        float4 v0 = *(const float4*)vr, v1 = *(const float4*)(vr + 4);
        Vs[vn + 0][vk] = f2t(v0.x); Vs[vn + 1][vk] = f2t(v0.y);
        Vs[vn + 2][vk] = f2t(v0.z); Vs[vn + 3][vk] = f2t(v0.w);
        Vs[vn + 4][vk] = f2t(v1.x); Vs[vn + 5][vk] = f2t(v1.y);
        Vs[vn + 6][vk] = f2t(v1.z); Vs[vn + 7][vk] = f2t(v1.w);
        __syncthreads();

#pragma unroll
        for (int ks = 0; ks < 16; ks += 8) {
            unsigned a[4][4], b[4][2];
#pragma unroll
            for (int mt = 0; mt < 4; mt++) {
                const int m0 = wm + mt * 16 + ar;
                a[mt][0] = As[ks + ak][m0];
                a[mt][1] = As[ks + ak][m0 + 8];
                a[mt][2] = As[ks + 4 + ak][m0];
                a[mt][3] = As[ks + 4 + ak][m0 + 8];
            }
#pragma unroll
            for (int nt = 0; nt < 4; nt++) {
                const int n0 = wn + nt * 8 + ar;
                b[nt][0] = Vs[n0][ks + ak];
                b[nt][1] = Vs[n0][ks + 4 + ak];
            }
#pragma unroll
            for (int mt = 0; mt < 4; mt++)
#pragma unroll
                for (int nt = 0; nt < 4; nt++) mma8(acc[mt][nt], a[mt], b[nt]);
        }
        __syncthreads();
    }

    const int b = bh >> 4, h = bh & 15;
    const int ac2 = (lane & 3) * 2;
#pragma unroll
    for (int nt = 0; nt < 4; nt++) {
        const int col = h * HDc + wn + nt * 8 + ac2;
#pragma unroll
        for (int mt = 0; mt < 4; mt++) {
            const int q = bm + wm + mt * 16 + ar;
            *(float2*)&g_outh[((size_t)(b * Sc + q)) * HIDc + col] =
                make_float2(acc[mt][nt][0], acc[mt][nt][1]);
            *(float2*)&g_outh[((size_t)(b * Sc + q + 8)) * HIDc + col] =
                make_float2(acc[mt][nt][2], acc[mt][nt][3]);
        }
    }
}

// ---------------- RoPE + scatter qkv -> Q/K/V in (B,NH,S,HD) ----------------
__global__ void rope_scatter(const int* __restrict__ pos)
{
    const int s = blockIdx.x, h = blockIdx.y, b = blockIdx.z, d = threadIdx.x;
    const size_t base = ((size_t)(b * Sc + s)) * (3 * HIDc) + (size_t)h * (3 * HDc);

    float qv = g_qkv[base + d];
    float kv = g_qkv[base + HDc + d];
    float vv = g_qkv[base + 2 * HDc + d];

    if (d < RDc) {
        const int i = d & 15;
        const float invf = exp2f(-((float)i * (1.0f / 16.0f)) * 13.28771237954945f);
        const float t = (float)pos[b * Sc + s];
        const float ang = t * invf;
        float sn, c;
        sincosf(ang, &sn, &c);
        if (d < 16) {
            qv = qv * c - g_qkv[base + d + 16] * sn;
            kv = kv * c - g_qkv[base + HDc + d + 16] * sn;
        } else {
            qv = qv * c + g_qkv[base + d - 16] * sn;
            kv = kv * c + g_qkv[base + HDc + d - 16] * sn;
        }
    }
    const size_t o = ((size_t)((b * NHc + h) * Sc) + s) * HDc + d;
    g_q[o] = qv; g_k[o] = kv; g_v[o] = vv;
}

// ---------------- causal row softmax (register-resident values) ----------------
__global__ __launch_bounds__(256) void softmax_kernel(const float* __restrict__ amask)
{
    const int row = blockIdx.x;            // b*NH*S + h*S + q
    const int q  = row & (Sc - 1);
    const int bh = row >> 11;
    const int b  = bh >> 4;                // / NHc
    float* ap = g_attn + (size_t)row * Sc;
    const float* mp = amask + (size_t)b * Sc;

    const int tid = threadIdx.x, lane = tid & 31, w = tid >> 5;
    const int n = q + 1;
    __shared__ float sred[8];

    float vals[8];
    float lm = -3.4e38f;
#pragma unroll
    for (int i = 0; i < 8; i++) {
        const int k = tid + i * 256;
        float v = -3.4e38f;
        if (k < n) v = ap[k] + mp[k];
        vals[i] = v;
        lm = fmaxf(lm, v);
    }
#pragma unroll
    for (int o = 16; o > 0; o >>= 1) lm = fmaxf(lm, __shfl_xor_sync(0xffffffffu, lm, o));
    if (lane == 0) sred[w] = lm;
    __syncthreads();
    float m = sred[0];
#pragma unroll
    for (int i = 1; i < 8; i++) m = fmaxf(m, sred[i]);
    __syncthreads();

    float ls = 0.f;
#pragma unroll
    for (int i = 0; i < 8; i++) {
        const int k = tid + i * 256;
        if (k < n) {
            float e = __expf(vals[i] - m);
            vals[i] = e;
            ls += e;
        }
    }
#pragma unroll
    for (int o = 16; o > 0; o >>= 1) ls += __shfl_xor_sync(0xffffffffu, ls, o);
    if (lane == 0) sred[w] = ls;
    __syncthreads();
    float s = 0.f;
#pragma unroll
    for (int i = 0; i < 8; i++) s += sred[i];
    const float inv = 1.0f / s;

#pragma unroll
    for (int i = 0; i < 8; i++) {
        const int k = tid + i * 256;
        if (k < n) ap[k] = vals[i] * inv;
    }
}

// ---------------- column sums over q (and last-MB window), summed over b ----------------
__global__ void colreduce_kernel()
{
    const int k = blockIdx.x * 256 + threadIdx.x;
    const int h = blockIdx.y;
    const int q0 = blockIdx.x * 256;
    float s = 0.f, r = 0.f;
    for (int b = 0; b < Bc; b++) {
        const float* ap = g_attn + ((size_t)(b * NHc + h)) * Sc * Sc;
        for (int q = q0; q < Sc; q++) {
            if (q >= k) {
                float a = ap[(size_t)q * Sc + k];
                s += a;
                if (q >= Sc - MBc) r += a;
            }
        }
    }
    g_colsum[h * Sc + k] = s;
    g_ratio [h * Sc + k] = r;
}

// ---------------- top-k per head (jax tie-break: lowest index) ----------------
__global__ __launch_bounds__(256) void topk_kernel()
{
    const int h = blockIdx.x, tid = threadIdx.x;
    __shared__ float tv[NCAND];
    __shared__ float rv[256];
    __shared__ int   ri[256];

    for (int i = tid; i < NCAND; i += 256) tv[i] = g_colsum[h * Sc + SBc + i];
    __syncthreads();

    for (int r = 0; r < TKc; r++) {
        float bv = -1e30f; int bi = NCAND;
        for (int i = tid; i < NCAND; i += 256) {
            float v = tv[i];
            if (v > bv) { bv = v; bi = i; }
        }
        rv[tid] = bv; ri[tid] = bi;
        __syncthreads();
        for (int st = 128; st > 0; st >>= 1) {
            if (tid < st) {
                if (rv[tid + st] > rv[tid] ||
                    (rv[tid + st] == rv[tid] && ri[tid + st] < ri[tid])) {
                    rv[tid] = rv[tid + st]; ri[tid] = ri[tid + st];
                }
            }
            __syncthreads();
        }
        if (tid == 0) {
            const int gi = ri[0] + SBc;
            g_topidx[h * TKc + r] = gi;
            g_topval[h * TKc + r] = g_ratio[h * Sc + gi] * (1.0f / MBc);
            tv[ri[0]] = -1e30f;
        }
        __syncthreads();
    }
}

// ---------------- v[b,h,SB,:] = sum_j v[b,h,idx_j,:] * val_j ----------------
__global__ void vupdate_kernel()
{
    const int bh = blockIdx.x;
    const int h  = bh % NHc;
    const int d  = threadIdx.x;
    float* vp = g_v + (size_t)bh * Sc * HDc;
    float acc = 0.f;
#pragma unroll
    for (int j = 0; j < TKc; j++)
        acc += vp[(size_t)g_topidx[h * TKc + j] * HDc + d] * g_topval[h * TKc + j];
    vp[(size_t)SBc * HDc + d] = acc;
}

// ---------------- launch ----------------
extern "C" void kernel_launch(void* const* d_in, const int* in_sizes, int n_in,
                              void* d_out, int out_size)
{
    (void)in_sizes; (void)n_in; (void)out_size;
    const float* hs    = (const float*)d_in[0];
    const float* amask = (const float*)d_in[1];
    const int*   pos   = (const int*)  d_in[2];
    const float* Wqkv  = (const float*)d_in[3];
    const float* bqkv  = (const float*)d_in[4];
    const float* Wd    = (const float*)d_in[5];
    const float* bd    = (const float*)d_in[6];
    float* out = (float*)d_out;

    void *p_qkv = nullptr, *p_outh = nullptr;
    cudaGetSymbolAddress(&p_qkv, g_qkv);
    cudaGetSymbolAddress(&p_outh, g_outh);

    // 1. QKV projection (TF32 tensor cores)
    gemm_tn_tc<<<dim3(3 * HIDc / 128, (Bc * Sc) / 128), 256>>>(
        hs, Wqkv, bqkv, (float*)p_qkv, Bc * Sc, 3 * HIDc, HIDc);

    // 2. RoPE + scatter
    rope_scatter<<<dim3(Sc, NHc, Bc), HDc>>>(pos);

    // 3. scaled QK^T (causal tiles only, TF32)
    scores_tc<<<dim3(Sc / 128, Sc / 128, Bc * NHc), 256>>>();

    // 4. row softmax
    softmax_kernel<<<Bc * NHc * Sc, 256>>>(amask);

    // 5. column statistics
    colreduce_kernel<<<dim3(Sc / 256, NHc), 256>>>();

    // 6. per-head top-16
    topk_kernel<<<NHc, 256>>>();

    // 7. merged row write into v
    vupdate_kernel<<<Bc * NHc, HDc>>>();

    // 8. attn @ v (TF32)
    attnv_tc<<<dim3(Sc / 128, Bc * NHc), 256>>>();

    // 9. dense projection (TF32)
    gemm_tn_tc<<<dim3(HIDc / 128, (Bc * Sc) / 128), 256>>>(
        (const float*)p_outh, Wd, bd, out, Bc * Sc, HIDc, HIDc);
}

// round 8
// speedup vs baseline: 1.7218x; 1.2215x over previous
#include <cuda_runtime.h>
#include <math.h>

// ---------------- problem constants ----------------
constexpr int Bc   = 2;
constexpr int Sc   = 2048;
constexpr int HIDc = 2048;
constexpr int NHc  = 16;
constexpr int HDc  = 128;
constexpr int RDc  = 32;
constexpr int SBc  = 204;           // int(0.1 * S)
constexpr int RBc  = 204;           // int(0.1 * S)
constexpr int MBc  = 128;           // MERGE_BUDGET
constexpr int TKc  = 16;            // TOPK
constexpr int NCAND = Sc - RBc - SBc;   // 1640 candidates
constexpr int NQCH = 8;             // colreduce q-chunks

// ---------------- device scratch (static, allocation-free) ----------------
__device__ float g_q   [(size_t)Bc * NHc * Sc * HDc];    //  32 MB
__device__ float g_k   [(size_t)Bc * NHc * Sc * HDc];    //  32 MB
__device__ float g_v   [(size_t)Bc * NHc * Sc * HDc];    //  32 MB
__device__ float g_attn[(size_t)Bc * NHc * Sc * Sc];     // 512 MB
__device__ float g_outh[(size_t)Bc * Sc * HIDc];         //  32 MB
__device__ float g_colpart[(size_t)NQCH * NHc * Sc];
__device__ float g_colsum[NHc * Sc];
__device__ float g_ratio [NHc * Sc];
__device__ int   g_topidx[NHc * TKc];
__device__ float g_topval[NHc * TKc];

// ---------------- tf32 helpers ----------------
__device__ __forceinline__ unsigned f2t(float x) {
    unsigned r; asm("cvt.rna.tf32.f32 %0, %1;" : "=r"(r) : "f"(x)); return r;
}
__device__ __forceinline__ void mma8(float* c, const unsigned* a, const unsigned* b) {
    asm volatile(
        "mma.sync.aligned.m16n8k8.row.col.f32.tf32.tf32.f32 "
        "{%0,%1,%2,%3}, {%4,%5,%6,%7}, {%8,%9}, {%0,%1,%2,%3};"
        : "+f"(c[0]), "+f"(c[1]), "+f"(c[2]), "+f"(c[3])
        : "r"(a[0]), "r"(a[1]), "r"(a[2]), "r"(a[3]), "r"(b[0]), "r"(b[1]));
}

// store one 8-deep K slice (converted to tf32) into a [16][132] tile
#define STS8(ARR, BUFI, V0, V1)                                               \
    ARR[BUFI][lkh+0][lrow]=f2t(V0.x); ARR[BUFI][lkh+1][lrow]=f2t(V0.y);       \
    ARR[BUFI][lkh+2][lrow]=f2t(V0.z); ARR[BUFI][lkh+3][lrow]=f2t(V0.w);       \
    ARR[BUFI][lkh+4][lrow]=f2t(V1.x); ARR[BUFI][lkh+5][lrow]=f2t(V1.y);       \
    ARR[BUFI][lkh+6][lrow]=f2t(V1.z); ARR[BUFI][lkh+7][lrow]=f2t(V1.w);

// warp-tile compute: A,B both [16][132] k-major tiles
#define COMPUTE_TILE(ASRC, BSRC)                                              \
    _Pragma("unroll")                                                         \
    for (int ks = 0; ks < 16; ks += 8) {                                      \
        unsigned afr[4][4], bfr[4][2];                                        \
        _Pragma("unroll")                                                     \
        for (int mt = 0; mt < 4; mt++) {                                      \
            const int m0 = wm + mt*16 + ar;                                   \
            afr[mt][0] = ASRC[ks+ak][m0];                                     \
            afr[mt][1] = ASRC[ks+ak][m0+8];                                   \
            afr[mt][2] = ASRC[ks+4+ak][m0];                                   \
            afr[mt][3] = ASRC[ks+4+ak][m0+8];                                 \
        }                                                                     \
        _Pragma("unroll")                                                     \
        for (int nt = 0; nt < 4; nt++) {                                      \
            const int n0 = wn + nt*8 + ar;                                    \
            bfr[nt][0] = BSRC[ks+ak][n0];                                     \
            bfr[nt][1] = BSRC[ks+4+ak][n0];                                   \
        }                                                                     \
        _Pragma("unroll")                                                     \
        for (int mt = 0; mt < 4; mt++)                                        \
            _Pragma("unroll")                                                 \
            for (int nt = 0; nt < 4; nt++)                                    \
                mma8(acc[mt][nt], afr[mt], bfr[nt]);                          \
    }

// ================= QKV GEMM (TF32, double-buffered) with scatter epilogue ===
// C row r0 -> (b, s); col -> (head h, q/k/v select, dim d). Writes g_q/g_k/g_v.
__global__ __launch_bounds__(256) void qkv_gemm_tc(
    const float* __restrict__ A, const float* __restrict__ Bm,
    const float* __restrict__ bias,
    float* __restrict__ qb, float* __restrict__ kb, float* __restrict__ vb)
{
    constexpr int K = HIDc;
    __shared__ unsigned As[2][16][132];
    __shared__ unsigned Bs[2][16][132];

    const int tid = threadIdx.x, lane = tid & 31, w = tid >> 5;
    const int bm = blockIdx.y * 128, bn = blockIdx.x * 128;
    const int wm = (w >> 2) * 64, wn = (w & 3) * 32;
    const int lrow = tid & 127, lkh = (tid >> 7) * 8;
    const int ar = lane >> 2, ak = lane & 3;

    const float* Ap = A  + (size_t)(bm + lrow) * K + lkh;
    const float* Bp = Bm + (size_t)(bn + lrow) * K + lkh;

    float acc[4][4][4];
#pragma unroll
    for (int mt = 0; mt < 4; mt++)
#pragma unroll
        for (int nt = 0; nt < 4; nt++)
#pragma unroll
            for (int i = 0; i < 4; i++) acc[mt][nt][i] = 0.f;

    float4 pa0 = *(const float4*)Ap, pa1 = *(const float4*)(Ap + 4);
    float4 pb0 = *(const float4*)Bp, pb1 = *(const float4*)(Bp + 4);
    STS8(As, 0, pa0, pa1);
    STS8(Bs, 0, pb0, pb1);
    __syncthreads();

    int buf = 0;
    for (int k0 = 0; k0 < K; k0 += 16) {
        const bool more = (k0 + 16 < K);
        if (more) {
            pa0 = *(const float4*)(Ap + k0 + 16); pa1 = *(const float4*)(Ap + k0 + 20);
            pb0 = *(const float4*)(Bp + k0 + 16); pb1 = *(const float4*)(Bp + k0 + 20);
        }
        COMPUTE_TILE(As[buf], Bs[buf]);
        if (more) {
            const int nb = buf ^ 1;
            STS8(As, nb, pa0, pa1);
            STS8(Bs, nb, pb0, pb1);
        }
        __syncthreads();
        buf ^= 1;
    }

    const int ac2 = (lane & 3) * 2;
#pragma unroll
    for (int nt = 0; nt < 4; nt++) {
        const int col = bn + wn + nt * 8 + ac2;
        const int h = col / 384;
        const int r = col - h * 384;
        float* basep = (r < 128) ? qb : (r < 256) ? kb : vb;
        const int d = r & 127;
        const float b0 = bias[col], b1 = bias[col + 1];
#pragma unroll
        for (int mt = 0; mt < 4; mt++) {
            const int r0 = bm + wm + mt * 16 + ar;
            const int bb = r0 >> 11, s = r0 & 2047;
            float* dst = basep + (((size_t)(bb * NHc + h) * Sc + s) * HDc + d);
            *(float2*)dst = make_float2(acc[mt][nt][0] + b0, acc[mt][nt][1] + b1);
            *(float2*)(dst + (size_t)8 * HDc) =
                make_float2(acc[mt][nt][2] + b0, acc[mt][nt][3] + b1);
        }
    }
}

// ---------------- RoPE in place on first RD dims of g_q / g_k ----------------
__global__ void rope_inplace(const int* __restrict__ pos)
{
    const int s = blockIdx.x, h = blockIdx.y, b = blockIdx.z;
    const int t = threadIdx.x;                 // 0..63; warp0 = q, warp1 = k
    const int d = t & 31;
    float* base = ((t < 32) ? g_q : g_k) + (((size_t)(b * NHc + h) * Sc + s) * HDc);
    float x = base[d];
    float partner = __shfl_xor_sync(0xffffffffu, x, 16);
    const int i = d & 15;
    const float invf = exp2f(-((float)i * (1.0f / 16.0f)) * 13.28771237954945f);
    const float ang = (float)pos[b * Sc + s] * invf;
    float sn, c;
    sincosf(ang, &sn, &c);
    base[d] = (d < 16) ? (x * c - partner * sn) : (x * c + partner * sn);
}

// ================= scores = scale * Q K^T (TF32, causal tiles, dbuf) =========
__global__ __launch_bounds__(256) void scores_tc()
{
    if (blockIdx.x > blockIdx.y) return;
    constexpr float SCALE = 0.08838834764831845f;  // 1/sqrt(128)
    __shared__ unsigned As[2][16][132];
    __shared__ unsigned Bs[2][16][132];

    const int tid = threadIdx.x, lane = tid & 31, w = tid >> 5;
    const int bh = blockIdx.z;
    const int bm = blockIdx.y * 128, bn = blockIdx.x * 128;
    const int wm = (w >> 2) * 64, wn = (w & 3) * 32;
    const int lrow = tid & 127, lkh = (tid >> 7) * 8;
    const int ar = lane >> 2, ak = lane & 3;

    const float* Ap = g_q + (size_t)bh * Sc * HDc + (size_t)(bm + lrow) * HDc + lkh;
    const float* Bp = g_k + (size_t)bh * Sc * HDc + (size_t)(bn + lrow) * HDc + lkh;
    float* C = g_attn + (size_t)bh * Sc * Sc;

    float acc[4][4][4];
#pragma unroll
    for (int mt = 0; mt < 4; mt++)
#pragma unroll
        for (int nt = 0; nt < 4; nt++)
#pragma unroll
            for (int i = 0; i < 4; i++) acc[mt][nt][i] = 0.f;

    float4 pa0 = *(const float4*)Ap, pa1 = *(const float4*)(Ap + 4);
    float4 pb0 = *(const float4*)Bp, pb1 = *(const float4*)(Bp + 4);
    STS8(As, 0, pa0, pa1);
    STS8(Bs, 0, pb0, pb1);
    __syncthreads();

    int buf = 0;
    for (int k0 = 0; k0 < HDc; k0 += 16) {
        const bool more = (k0 + 16 < HDc);
        if (more) {
            pa0 = *(const float4*)(Ap + k0 + 16); pa1 = *(const float4*)(Ap + k0 + 20);
            pb0 = *(const float4*)(Bp + k0 + 16); pb1 = *(const float4*)(Bp + k0 + 20);
        }
        COMPUTE_TILE(As[buf], Bs[buf]);
        if (more) {
            const int nb = buf ^ 1;
            STS8(As, nb, pa0, pa1);
            STS8(Bs, nb, pb0, pb1);
        }
        __syncthreads();
        buf ^= 1;
    }

    const int ac2 = (lane & 3) * 2;
#pragma unroll
    for (int nt = 0; nt < 4; nt++) {
        const int col = bn + wn + nt * 8 + ac2;
#pragma unroll
        for (int mt = 0; mt < 4; mt++) {
            const int r0 = bm + wm + mt * 16 + ar;
            *(float2*)&C[(size_t)r0 * Sc + col] =
                make_float2(acc[mt][nt][0] * SCALE, acc[mt][nt][1] * SCALE);
            *(float2*)&C[(size_t)(r0 + 8) * Sc + col] =
                make_float2(acc[mt][nt][2] * SCALE, acc[mt][nt][3] * SCALE);
        }
    }
}

// ---------------- causal row softmax, float4 over valid groups ----------------
__global__ __launch_bounds__(256) void softmax_kernel(const float* __restrict__ amask)
{
    const int row = blockIdx.x;
    const int q = row & (Sc - 1);
    const int b = row >> 15;               // / (NHc*Sc)
    float* ap = g_attn + (size_t)row * Sc;
    const float* mp = amask + (size_t)b * Sc;

    const int tid = threadIdx.x, lane = tid & 31, w = tid >> 5;
    __shared__ float sred[8];

    const int nv = (q >> 2) + 1;           // float4 groups covering [0, q]
    float4 x[2];
    float lm = -3.4e38f;
#pragma unroll
    for (int it = 0; it < 2; it++) {
        const int g = tid + it * 256;
        if (g < nv) {
            float4 v = *(const float4*)(ap + g * 4);
            float4 m = *(const float4*)(mp + g * 4);
            const int k = g * 4;
            v.x = (k + 0 <= q) ? v.x + m.x : -3.4e38f;
            v.y = (k + 1 <= q) ? v.y + m.y : -3.4e38f;
            v.z = (k + 2 <= q) ? v.z + m.z : -3.4e38f;
            v.w = (k + 3 <= q) ? v.w + m.w : -3.4e38f;
            x[it] = v;
            lm = fmaxf(lm, fmaxf(fmaxf(v.x, v.y), fmaxf(v.z, v.w)));
        } else {
            x[it] = make_float4(-3.4e38f, -3.4e38f, -3.4e38f, -3.4e38f);
        }
    }
#pragma unroll
    for (int o = 16; o > 0; o >>= 1) lm = fmaxf(lm, __shfl_xor_sync(0xffffffffu, lm, o));
    if (lane == 0) sred[w] = lm;
    __syncthreads();
    float m = sred[0];
#pragma unroll
    for (int i = 1; i < 8; i++) m = fmaxf(m, sred[i]);
    __syncthreads();

    float ls = 0.f;
#pragma unroll
    for (int it = 0; it < 2; it++) {
        const int g = tid + it * 256;
        if (g < nv) {
            float4 v = x[it];
            v.x = __expf(v.x - m); v.y = __expf(v.y - m);
            v.z = __expf(v.z - m); v.w = __expf(v.w - m);
            x[it] = v;
            ls += v.x + v.y + v.z + v.w;
        }
    }
#pragma unroll
    for (int o = 16; o > 0; o >>= 1) ls += __shfl_xor_sync(0xffffffffu, ls, o);
    if (lane == 0) sred[w] = ls;
    __syncthreads();
    float s = 0.f;
#pragma unroll
    for (int i = 0; i < 8; i++) s += sred[i];
    const float inv = 1.0f / s;

#pragma unroll
    for (int it = 0; it < 2; it++) {
        const int g = tid + it * 256;
        if (g < nv) {
            float4 v = x[it];
            *(float4*)(ap + g * 4) =
                make_float4(v.x * inv, v.y * inv, v.z * inv, v.w * inv);
        }
    }
}

// ---------------- column-sum partials per q-chunk (deterministic) ----------------
__global__ void colpart_kernel()
{
    const int k = blockIdx.x * 256 + threadIdx.x;
    const int h = blockIdx.y;
    const int z = blockIdx.z;
    float s = 0.f, r = 0.f;
    if (z >= (int)blockIdx.x) {            // chunk can contain q >= k
        const int qlo = z * 256, qhi = qlo + 256;
        for (int b = 0; b < Bc; b++) {
            const float* ap = g_attn + ((size_t)(b * NHc + h)) * Sc * Sc;
            for (int q = qlo; q < qhi; q++) {
                if (q >= k) {
                    float a = ap[(size_t)q * Sc + k];
                    s += a;
                    if (q >= Sc - MBc) r += a;
                }
            }
        }
    }
    g_colpart[((size_t)z * NHc + h) * Sc + k] = s;
    if (z == NQCH - 1) g_ratio[h * Sc + k] = r;
}

__global__ void colsumfin_kernel()
{
    const int k = blockIdx.x * 256 + threadIdx.x;
    const int h = blockIdx.y;
    float s = 0.f;
#pragma unroll
    for (int z = 0; z < NQCH; z++) s += g_colpart[((size_t)z * NHc + h) * Sc + k];
    g_colsum[h * Sc + k] = s;
}

// ---------------- top-k per head (jax tie-break: lowest index) ----------------
__global__ __launch_bounds__(256) void topk_kernel()
{
    const int h = blockIdx.x, tid = threadIdx.x;
    __shared__ float tv[NCAND];
    __shared__ float rv[256];
    __shared__ int   ri[256];

    for (int i = tid; i < NCAND; i += 256) tv[i] = g_colsum[h * Sc + SBc + i];
    __syncthreads();

    for (int r = 0; r < TKc; r++) {
        float bv = -1e30f; int bi = NCAND;
        for (int i = tid; i < NCAND; i += 256) {
            float v = tv[i];
            if (v > bv) { bv = v; bi = i; }
        }
        rv[tid] = bv; ri[tid] = bi;
        __syncthreads();
        for (int st = 128; st > 0; st >>= 1) {
            if (tid < st) {
                if (rv[tid + st] > rv[tid] ||
                    (rv[tid + st] == rv[tid] && ri[tid + st] < ri[tid])) {
                    rv[tid] = rv[tid + st]; ri[tid] = ri[tid + st];
                }
            }
            __syncthreads();
        }
        if (tid == 0) {
            const int gi = ri[0] + SBc;
            g_topidx[h * TKc + r] = gi;
            g_topval[h * TKc + r] = g_ratio[h * Sc + gi] * (1.0f / MBc);
            tv[ri[0]] = -1e30f;
        }
        __syncthreads();
    }
}

// ---------------- v[b,h,SB,:] = sum_j v[b,h,idx_j,:] * val_j ----------------
__global__ void vupdate_kernel()
{
    const int bh = blockIdx.x;
    const int h  = bh % NHc;
    const int d  = threadIdx.x;
    float* vp = g_v + (size_t)bh * Sc * HDc;
    float acc = 0.f;
#pragma unroll
    for (int j = 0; j < TKc; j++)
        acc += vp[(size_t)g_topidx[h * TKc + j] * HDc + d] * g_topval[h * TKc + j];
    vp[(size_t)SBc * HDc + d] = acc;
}

// ================= out = attn @ v (TF32, causal, dbuf), scatter ==============
__global__ __launch_bounds__(256) void attnv_tc()
{
    __shared__ unsigned As[2][16][132];   // [k][m]
    __shared__ unsigned Vs[2][128][20];   // [n][k]

    const int tid = threadIdx.x, lane = tid & 31, w = tid >> 5;
    const int bh = blockIdx.y;
    const int bm = blockIdx.x * 128;
    const int wm = (w >> 2) * 64, wn = (w & 3) * 32;
    const int ar = lane >> 2, ak = lane & 3;

    const float* attn = g_attn + (size_t)bh * Sc * Sc;
    const float* vp   = g_v    + (size_t)bh * Sc * HDc;

    const int lrow = tid & 127, lkh = (tid >> 7) * 8;
    const int q_l = bm + lrow;
    const float* arow = attn + (size_t)q_l * Sc;
    const int vk = tid & 15, vn = (tid >> 4) * 8;

    float acc[4][4][4];
#pragma unroll
    for (int mt = 0; mt < 4; mt++)
#pragma unroll
        for (int nt = 0; nt < 4; nt++)
#pragma unroll
            for (int i = 0; i < 4; i++) acc[mt][nt][i] = 0.f;

    const int kend = bm + 128;

#define STS_A_MASKED(BUFI, V0, V1, KB)                                        \
    As[BUFI][lkh+0][lrow] = ((KB)+0 <= q_l) ? f2t(V0.x) : 0u;                 \
    As[BUFI][lkh+1][lrow] = ((KB)+1 <= q_l) ? f2t(V0.y) : 0u;                 \
    As[BUFI][lkh+2][lrow] = ((KB)+2 <= q_l) ? f2t(V0.z) : 0u;                 \
    As[BUFI][lkh+3][lrow] = ((KB)+3 <= q_l) ? f2t(V0.w) : 0u;                 \
    As[BUFI][lkh+4][lrow] = ((KB)+4 <= q_l) ? f2t(V1.x) : 0u;                 \
    As[BUFI][lkh+5][lrow] = ((KB)+5 <= q_l) ? f2t(V1.y) : 0u;                 \
    As[BUFI][lkh+6][lrow] = ((KB)+6 <= q_l) ? f2t(V1.z) : 0u;                 \
    As[BUFI][lkh+7][lrow] = ((KB)+7 <= q_l) ? f2t(V1.w) : 0u;

#define STS_V(BUFI, V0, V1)                                                   \
    Vs[BUFI][vn+0][vk]=f2t(V0.x); Vs[BUFI][vn+1][vk]=f2t(V0.y);               \
    Vs[BUFI][vn+2][vk]=f2t(V0.z); Vs[BUFI][vn+3][vk]=f2t(V0.w);               \
    Vs[BUFI][vn+4][vk]=f2t(V1.x); Vs[BUFI][vn+5][vk]=f2t(V1.y);               \
    Vs[BUFI][vn+6][vk]=f2t(V1.z); Vs[BUFI][vn+7][vk]=f2t(V1.w);

    // prologue: tile k0 = 0
    {
        float4 a0v = *(const float4*)(arow + lkh);
        float4 a1v = *(const float4*)(arow + lkh + 4);
        STS_A_MASKED(0, a0v, a1v, lkh);
        const float* vr = vp + (size_t)vk * HDc + vn;
        float4 v0 = *(const float4*)vr, v1 = *(const float4*)(vr + 4);
        STS_V(0, v0, v1);
    }
    __syncthreads();

    int buf = 0;
    for (int k0 = 0; k0 < kend; k0 += 16) {
        const bool more = (k0 + 16 < kend);
        float4 a0v, a1v, v0, v1;
        if (more) {
            a0v = *(const float4*)(arow + k0 + 16 + lkh);
            a1v = *(const float4*)(arow + k0 + 20 + lkh);
            const float* vr = vp + (size_t)(k0 + 16 + vk) * HDc + vn;
            v0 = *(const float4*)vr; v1 = *(const float4*)(vr + 4);
        }

#pragma unroll
        for (int ks = 0; ks < 16; ks += 8) {
            unsigned afr[4][4], bfr[4][2];
#pragma unroll
            for (int mt = 0; mt < 4; mt++) {
                const int m0 = wm + mt * 16 + ar;
                afr[mt][0] = As[buf][ks+ak][m0];
                afr[mt][1] = As[buf][ks+ak][m0+8];
                afr[mt][2] = As[buf][ks+4+ak][m0];
                afr[mt][3] = As[buf][ks+4+ak][m0+8];
            }
#pragma unroll
            for (int nt = 0; nt < 4; nt++) {
                const int n0 = wn + nt * 8 + ar;
                bfr[nt][0] = Vs[buf][n0][ks+ak];
                bfr[nt][1] = Vs[buf][n0][ks+4+ak];
            }
#pragma unroll
            for (int mt = 0; mt < 4; mt++)
#pragma unroll
                for (int nt = 0; nt < 4; nt++) mma8(acc[mt][nt], afr[mt], bfr[nt]);
        }

        if (more) {
            const int nb = buf ^ 1;
            const int kb2 = k0 + 16 + lkh;
            STS_A_MASKED(nb, a0v, a1v, kb2);
            STS_V(nb, v0, v1);
        }
        __syncthreads();
        buf ^= 1;
    }

    const int b = bh >> 4, h = bh & 15;
    const int ac2 = (lane & 3) * 2;
#pragma unroll
    for (int nt = 0; nt < 4; nt++) {
        const int col = h * HDc + wn + nt * 8 + ac2;
#pragma unroll
        for (int mt = 0; mt < 4; mt++) {
            const int q = bm + wm + mt * 16 + ar;
            *(float2*)&g_outh[((size_t)(b * Sc + q)) * HIDc + col] =
                make_float2(acc[mt][nt][0], acc[mt][nt][1]);
            *(float2*)&g_outh[((size_t)(b * Sc + q + 8)) * HIDc + col] =
                make_float2(acc[mt][nt][2], acc[mt][nt][3]);
        }
    }
#undef STS_A_MASKED
#undef STS_V
}

// ================= dense TF32 TN GEMM (double-buffered) ======================
__global__ __launch_bounds__(256) void gemm_tn_tc(
    const float* __restrict__ A, const float* __restrict__ Bm,
    const float* __restrict__ bias, float* __restrict__ C,
    int M, int N, int K)
{
    __shared__ unsigned As[2][16][132];
    __shared__ unsigned Bs[2][16][132];

    const int tid = threadIdx.x, lane = tid & 31, w = tid >> 5;
    const int bm = blockIdx.y * 128, bn = blockIdx.x * 128;
    const int wm = (w >> 2) * 64, wn = (w & 3) * 32;
    const int lrow = tid & 127, lkh = (tid >> 7) * 8;
    const int ar = lane >> 2, ak = lane & 3;

    const float* Ap = A  + (size_t)(bm + lrow) * K + lkh;
    const float* Bp = Bm + (size_t)(bn + lrow) * K + lkh;

    float acc[4][4][4];
#pragma unroll
    for (int mt = 0; mt < 4; mt++)
#pragma unroll
        for (int nt = 0; nt < 4; nt++)
#pragma unroll
            for (int i = 0; i < 4; i++) acc[mt][nt][i] = 0.f;

    float4 pa0 = *(const float4*)Ap, pa1 = *(const float4*)(Ap + 4);
    float4 pb0 = *(const float4*)Bp, pb1 = *(const float4*)(Bp + 4);
    STS8(As, 0, pa0, pa1);
    STS8(Bs, 0, pb0, pb1);
    __syncthreads();

    int buf = 0;
    for (int k0 = 0; k0 < K; k0 += 16) {
        const bool more = (k0 + 16 < K);
        if (more) {
            pa0 = *(const float4*)(Ap + k0 + 16); pa1 = *(const float4*)(Ap + k0 + 20);
            pb0 = *(const float4*)(Bp + k0 + 16); pb1 = *(const float4*)(Bp + k0 + 20);
        }
        COMPUTE_TILE(As[buf], Bs[buf]);
        if (more) {
            const int nb = buf ^ 1;
            STS8(As, nb, pa0, pa1);
            STS8(Bs, nb, pb0, pb1);
        }
        __syncthreads();
        buf ^= 1;
    }

    const int ac2 = (lane & 3) * 2;
#pragma unroll
    for (int nt = 0; nt < 4; nt++) {
        const int col = bn + wn + nt * 8 + ac2;
        float b0 = 0.f, b1 = 0.f;
        if (bias) { b0 = bias[col]; b1 = bias[col + 1]; }
#pragma unroll
        for (int mt = 0; mt < 4; mt++) {
            const int r0 = bm + wm + mt * 16 + ar;
            *(float2*)&C[(size_t)r0 * N + col] =
                make_float2(acc[mt][nt][0] + b0, acc[mt][nt][1] + b1);
            *(float2*)&C[(size_t)(r0 + 8) * N + col] =
                make_float2(acc[mt][nt][2] + b0, acc[mt][nt][3] + b1);
        }
    }
}

// ---------------- launch ----------------
extern "C" void kernel_launch(void* const* d_in, const int* in_sizes, int n_in,
                              void* d_out, int out_size)
{
    (void)in_sizes; (void)n_in; (void)out_size;
    const float* hs    = (const float*)d_in[0];
    const float* amask = (const float*)d_in[1];
    const int*   pos   = (const int*)  d_in[2];
    const float* Wqkv  = (const float*)d_in[3];
    const float* bqkv  = (const float*)d_in[4];
    const float* Wd    = (const float*)d_in[5];
    const float* bd    = (const float*)d_in[6];
    float* out = (float*)d_out;

    void *p_q = nullptr, *p_k = nullptr, *p_v = nullptr, *p_outh = nullptr;
    cudaGetSymbolAddress(&p_q, g_q);
    cudaGetSymbolAddress(&p_k, g_k);
    cudaGetSymbolAddress(&p_v, g_v);
    cudaGetSymbolAddress(&p_outh, g_outh);

    // 1. QKV projection + per-head scatter (TF32, dbuf)
    qkv_gemm_tc<<<dim3(3 * HIDc / 128, (Bc * Sc) / 128), 256>>>(
        hs, Wqkv, bqkv, (float*)p_q, (float*)p_k, (float*)p_v);

    // 2. RoPE in place on rotary dims
    rope_inplace<<<dim3(Sc, NHc, Bc), 64>>>(pos);

    // 3. scaled QK^T (causal tiles, TF32, dbuf)
    scores_tc<<<dim3(Sc / 128, Sc / 128, Bc * NHc), 256>>>();

    // 4. row softmax (vectorized, causal groups only)
    softmax_kernel<<<Bc * NHc * Sc, 256>>>(amask);

    // 5a/5b. column statistics: per-chunk partials + fixed-order sum
    colpart_kernel<<<dim3(Sc / 256, NHc, NQCH), 256>>>();
    colsumfin_kernel<<<dim3(Sc / 256, NHc), 256>>>();

    // 6. per-head top-16
    topk_kernel<<<NHc, 256>>>();

    // 7. merged row write into v
    vupdate_kernel<<<Bc * NHc, HDc>>>();

    // 8. attn @ v (TF32, dbuf)
    attnv_tc<<<dim3(Sc / 128, Bc * NHc), 256>>>();

    // 9. dense projection (TF32, dbuf)
    gemm_tn_tc<<<dim3(HIDc / 128, (Bc * Sc) / 128), 256>>>(
        (const float*)p_outh, Wd, bd, out, Bc * Sc, HIDc, HIDc);
}

// round 11
// speedup vs baseline: 2.1363x; 1.2407x over previous
#include <cuda_runtime.h>
#include <math.h>

// ---------------- problem constants ----------------
constexpr int Bc   = 2;
constexpr int Sc   = 2048;
constexpr int HIDc = 2048;
constexpr int NHc  = 16;
constexpr int HDc  = 128;
constexpr int RDc  = 32;
constexpr int SBc  = 204;           // int(0.1 * S)
constexpr int RBc  = 204;           // int(0.1 * S)
constexpr int MBc  = 128;           // MERGE_BUDGET
constexpr int TKc  = 16;            // TOPK
constexpr int NCAND = Sc - RBc - SBc;   // 1640 candidates
constexpr int NQCH = 8;             // colreduce q-chunks

// ---------------- device scratch (static, allocation-free) ----------------
__device__ float g_q   [(size_t)Bc * NHc * Sc * HDc];    //  32 MB
__device__ float g_k   [(size_t)Bc * NHc * Sc * HDc];    //  32 MB
__device__ float g_v   [(size_t)Bc * NHc * Sc * HDc];    //  32 MB
__device__ float g_attn[(size_t)Bc * NHc * Sc * Sc];     // 512 MB
__device__ float g_outh[(size_t)Bc * Sc * HIDc];         //  32 MB
__device__ float g_colpart[(size_t)NQCH * NHc * Sc];
__device__ float g_colsum[NHc * Sc];
__device__ float g_ratio [NHc * Sc];
__device__ int   g_topidx[NHc * TKc];
__device__ float g_topval[NHc * TKc];

// ---------------- tf32 helpers ----------------
__device__ __forceinline__ unsigned f2t(float x) {
    unsigned r; asm("cvt.rna.tf32.f32 %0, %1;" : "=r"(r) : "f"(x)); return r;
}
__device__ __forceinline__ void mma8(float* c, const unsigned* a, const unsigned* b) {
    asm volatile(
        "mma.sync.aligned.m16n8k8.row.col.f32.tf32.tf32.f32 "
        "{%0,%1,%2,%3}, {%4,%5,%6,%7}, {%8,%9}, {%0,%1,%2,%3};"
        : "+f"(c[0]), "+f"(c[1]), "+f"(c[2]), "+f"(c[3])
        : "r"(a[0]), "r"(a[1]), "r"(a[2]), "r"(a[3]), "r"(b[0]), "r"(b[1]));
}

// store one 8-deep K slice (converted to tf32) into a [16][pad] tile
#define STS8(ARR, BUFI, V0, V1)                                               \
    ARR[BUFI][lkh+0][lrow]=f2t(V0.x); ARR[BUFI][lkh+1][lrow]=f2t(V0.y);       \
    ARR[BUFI][lkh+2][lrow]=f2t(V0.z); ARR[BUFI][lkh+3][lrow]=f2t(V0.w);       \
    ARR[BUFI][lkh+4][lrow]=f2t(V1.x); ARR[BUFI][lkh+5][lrow]=f2t(V1.y);       \
    ARR[BUFI][lkh+6][lrow]=f2t(V1.z); ARR[BUFI][lkh+7][lrow]=f2t(V1.w);

// warp-tile compute (4m x 4n of m16n8k8): A,B both [16][pad] k-major tiles
#define COMPUTE_TILE(ASRC, BSRC)                                              \
    _Pragma("unroll")                                                         \
    for (int ks = 0; ks < 16; ks += 8) {                                      \
        unsigned afr[4][4], bfr[4][2];                                        \
        _Pragma("unroll")                                                     \
        for (int mt = 0; mt < 4; mt++) {                                      \
            const int m0 = wm + mt*16 + ar;                                   \
            afr[mt][0] = ASRC[ks+ak][m0];                                     \
            afr[mt][1] = ASRC[ks+ak][m0+8];                                   \
            afr[mt][2] = ASRC[ks+4+ak][m0];                                   \
            afr[mt][3] = ASRC[ks+4+ak][m0+8];                                 \
        }                                                                     \
        _Pragma("unroll")                                                     \
        for (int nt = 0; nt < 4; nt++) {                                      \
            const int n0 = wn + nt*8 + ar;                                    \
            bfr[nt][0] = BSRC[ks+ak][n0];                                     \
            bfr[nt][1] = BSRC[ks+4+ak][n0];                                   \
        }                                                                     \
        _Pragma("unroll")                                                     \
        for (int mt = 0; mt < 4; mt++)                                        \
            _Pragma("unroll")                                                 \
            for (int nt = 0; nt < 4; nt++)                                    \
                mma8(acc[mt][nt], afr[mt], bfr[nt]);                          \
    }

// ============ 128M x 256N TF32 GEMM core (dynamic smem, dbuf) ============
// As: [2][16][136], Bs: [2][16][264]. 8 warps, warp tile 64x64.
// NOTE: variadic so the epilogue block may contain brace-level commas.
constexpr int APAD = 136, BPAD = 264;
constexpr int SMEMDYN = (2 * 16 * APAD + 2 * 16 * BPAD) * 4;

#define GEMM256_PROLOG_AND_LOOP(...)                                          \
    extern __shared__ unsigned smraw[];                                       \
    unsigned (*As)[16][APAD] = (unsigned(*)[16][APAD])smraw;                  \
    unsigned (*Bs)[16][BPAD] = (unsigned(*)[16][BPAD])(smraw + 2*16*APAD);    \
    const int tid = threadIdx.x, lane = tid & 31, w = tid >> 5;               \
    const int bm = blockIdx.y * 128, bn = blockIdx.x * 256;                   \
    const int wm = (w >> 2) * 64, wn = (w & 3) * 64;                          \
    const int lrow = tid & 127, lkh = (tid >> 7) * 8;                         \
    const int ar = lane >> 2, ak = lane & 3;                                  \
    const float* Ap  = A  + (size_t)(bm + lrow) * K + lkh;                    \
    const float* Bp0 = Bm + (size_t)(bn + lrow) * K + lkh;                    \
    const float* Bp1 = Bm + (size_t)(bn + lrow + 128) * K + lkh;              \
    float acc[4][8][4];                                                       \
    _Pragma("unroll")                                                         \
    for (int mt = 0; mt < 4; mt++)                                            \
        _Pragma("unroll")                                                     \
        for (int nt = 0; nt < 8; nt++)                                        \
            _Pragma("unroll")                                                 \
            for (int i = 0; i < 4; i++) acc[mt][nt][i] = 0.f;                 \
    float4 pa0 = *(const float4*)Ap,  pa1 = *(const float4*)(Ap + 4);         \
    float4 pb0 = *(const float4*)Bp0, pb1 = *(const float4*)(Bp0 + 4);        \
    float4 pc0 = *(const float4*)Bp1, pc1 = *(const float4*)(Bp1 + 4);        \
    {                                                                         \
        STS8(As, 0, pa0, pa1);                                                \
        STS8(Bs, 0, pb0, pb1);                                                \
        Bs[0][lkh+0][lrow+128]=f2t(pc0.x); Bs[0][lkh+1][lrow+128]=f2t(pc0.y); \
        Bs[0][lkh+2][lrow+128]=f2t(pc0.z); Bs[0][lkh+3][lrow+128]=f2t(pc0.w); \
        Bs[0][lkh+4][lrow+128]=f2t(pc1.x); Bs[0][lkh+5][lrow+128]=f2t(pc1.y); \
        Bs[0][lkh+6][lrow+128]=f2t(pc1.z); Bs[0][lkh+7][lrow+128]=f2t(pc1.w); \
    }                                                                         \
    __syncthreads();                                                          \
    int buf = 0;                                                              \
    for (int k0 = 0; k0 < K; k0 += 16) {                                      \
        const bool more = (k0 + 16 < K);                                      \
        if (more) {                                                           \
            pa0 = *(const float4*)(Ap  + k0 + 16); pa1 = *(const float4*)(Ap  + k0 + 20); \
            pb0 = *(const float4*)(Bp0 + k0 + 16); pb1 = *(const float4*)(Bp0 + k0 + 20); \
            pc0 = *(const float4*)(Bp1 + k0 + 16); pc1 = *(const float4*)(Bp1 + k0 + 20); \
        }                                                                     \
        _Pragma("unroll")                                                     \
        for (int ks = 0; ks < 16; ks += 8) {                                  \
            unsigned afr[4][4], bfr[8][2];                                    \
            _Pragma("unroll")                                                 \
            for (int mt = 0; mt < 4; mt++) {                                  \
                const int m0 = wm + mt*16 + ar;                               \
                afr[mt][0] = As[buf][ks+ak][m0];                              \
                afr[mt][1] = As[buf][ks+ak][m0+8];                            \
                afr[mt][2] = As[buf][ks+4+ak][m0];                            \
                afr[mt][3] = As[buf][ks+4+ak][m0+8];                          \
            }                                                                 \
            _Pragma("unroll")                                                 \
            for (int nt = 0; nt < 8; nt++) {                                  \
                const int n0 = wn + nt*8 + ar;                                \
                bfr[nt][0] = Bs[buf][ks+ak][n0];                              \
                bfr[nt][1] = Bs[buf][ks+4+ak][n0];                            \
            }                                                                 \
            _Pragma("unroll")                                                 \
            for (int mt = 0; mt < 4; mt++)                                    \
                _Pragma("unroll")                                             \
                for (int nt = 0; nt < 8; nt++)                                \
                    mma8(acc[mt][nt], afr[mt], bfr[nt]);                      \
        }                                                                     \
        if (more) {                                                           \
            const int nb = buf ^ 1;                                           \
            STS8(As, nb, pa0, pa1);                                           \
            STS8(Bs, nb, pb0, pb1);                                           \
            Bs[nb][lkh+0][lrow+128]=f2t(pc0.x); Bs[nb][lkh+1][lrow+128]=f2t(pc0.y); \
            Bs[nb][lkh+2][lrow+128]=f2t(pc0.z); Bs[nb][lkh+3][lrow+128]=f2t(pc0.w); \
            Bs[nb][lkh+4][lrow+128]=f2t(pc1.x); Bs[nb][lkh+5][lrow+128]=f2t(pc1.y); \
            Bs[nb][lkh+6][lrow+128]=f2t(pc1.z); Bs[nb][lkh+7][lrow+128]=f2t(pc1.w); \
        }                                                                     \
        __syncthreads();                                                      \
        buf ^= 1;                                                             \
    }                                                                         \
    __VA_ARGS__

// ================= QKV GEMM (128x256) with per-head scatter epilogue ========
__global__ __launch_bounds__(256) void qkv_gemm_tc(
    const float* __restrict__ A, const float* __restrict__ Bm,
    const float* __restrict__ bias,
    float* __restrict__ qb, float* __restrict__ kb, float* __restrict__ vb)
{
    constexpr int K = HIDc;
    GEMM256_PROLOG_AND_LOOP(
    {
        const int ac2 = (lane & 3) * 2;
        _Pragma("unroll")
        for (int nt = 0; nt < 8; nt++) {
            const int col = bn + wn + nt * 8 + ac2;
            const int h = col / 384;
            const int r = col - h * 384;
            float* basep = (r < 128) ? qb : (r < 256) ? kb : vb;
            const int d = r & 127;
            const float b0 = bias[col];
            const float b1 = bias[col + 1];
            _Pragma("unroll")
            for (int mt = 0; mt < 4; mt++) {
                const int r0 = bm + wm + mt * 16 + ar;
                const int bb = r0 >> 11;
                const int s = r0 & 2047;
                float* dst = basep + (((size_t)(bb * NHc + h) * Sc + s) * HDc + d);
                *(float2*)dst = make_float2(acc[mt][nt][0] + b0, acc[mt][nt][1] + b1);
                *(float2*)(dst + (size_t)8 * HDc) =
                    make_float2(acc[mt][nt][2] + b0, acc[mt][nt][3] + b1);
            }
        }
    })
}

// ================= dense GEMM (128x256), plain output =======================
__global__ __launch_bounds__(256) void gemm_tn_tc256(
    const float* __restrict__ A, const float* __restrict__ Bm,
    const float* __restrict__ bias, float* __restrict__ C,
    int M, int N, int K)
{
    GEMM256_PROLOG_AND_LOOP(
    {
        const int ac2 = (lane & 3) * 2;
        _Pragma("unroll")
        for (int nt = 0; nt < 8; nt++) {
            const int col = bn + wn + nt * 8 + ac2;
            const float b0 = bias[col];
            const float b1 = bias[col + 1];
            _Pragma("unroll")
            for (int mt = 0; mt < 4; mt++) {
                const int r0 = bm + wm + mt * 16 + ar;
                *(float2*)&C[(size_t)r0 * N + col] =
                    make_float2(acc[mt][nt][0] + b0, acc[mt][nt][1] + b1);
                *(float2*)&C[(size_t)(r0 + 8) * N + col] =
                    make_float2(acc[mt][nt][2] + b0, acc[mt][nt][3] + b1);
            }
        }
    })
}

// ---------------- RoPE in place on first RD dims of g_q / g_k ----------------
__global__ void rope_inplace(const int* __restrict__ pos)
{
    const int s = blockIdx.x, h = blockIdx.y, b = blockIdx.z;
    const int t = threadIdx.x;                 // 0..63; warp0 = q, warp1 = k
    const int d = t & 31;
    float* base = ((t < 32) ? g_q : g_k) + (((size_t)(b * NHc + h) * Sc + s) * HDc);
    float x = base[d];
    float partner = __shfl_xor_sync(0xffffffffu, x, 16);
    const int i = d & 15;
    const float invf = exp2f(-((float)i * (1.0f / 16.0f)) * 13.28771237954945f);
    const float ang = (float)pos[b * Sc + s] * invf;
    float sn, c;
    sincosf(ang, &sn, &c);
    base[d] = (d < 16) ? (x * c - partner * sn) : (x * c + partner * sn);
}

// ================= scores = scale * Q K^T (TF32, causal tiles, dbuf) =========
__global__ __launch_bounds__(256) void scores_tc()
{
    if (blockIdx.x > blockIdx.y) return;
    constexpr float SCALE = 0.08838834764831845f;  // 1/sqrt(128)
    __shared__ unsigned As[2][16][APAD];
    __shared__ unsigned Bs[2][16][APAD];

    const int tid = threadIdx.x, lane = tid & 31, w = tid >> 5;
    const int bh = blockIdx.z;
    const int bm = blockIdx.y * 128, bn = blockIdx.x * 128;
    const int wm = (w >> 2) * 64, wn = (w & 3) * 32;
    const int lrow = tid & 127, lkh = (tid >> 7) * 8;
    const int ar = lane >> 2, ak = lane & 3;

    const float* Ap = g_q + (size_t)bh * Sc * HDc + (size_t)(bm + lrow) * HDc + lkh;
    const float* Bp = g_k + (size_t)bh * Sc * HDc + (size_t)(bn + lrow) * HDc + lkh;
    float* C = g_attn + (size_t)bh * Sc * Sc;

    float acc[4][4][4];
#pragma unroll
    for (int mt = 0; mt < 4; mt++)
#pragma unroll
        for (int nt = 0; nt < 4; nt++)
#pragma unroll
            for (int i = 0; i < 4; i++) acc[mt][nt][i] = 0.f;

    float4 pa0 = *(const float4*)Ap, pa1 = *(const float4*)(Ap + 4);
    float4 pb0 = *(const float4*)Bp, pb1 = *(const float4*)(Bp + 4);
    STS8(As, 0, pa0, pa1);
    STS8(Bs, 0, pb0, pb1);
    __syncthreads();

    int buf = 0;
    for (int k0 = 0; k0 < HDc; k0 += 16) {
        const bool more = (k0 + 16 < HDc);
        if (more) {
            pa0 = *(const float4*)(Ap + k0 + 16); pa1 = *(const float4*)(Ap + k0 + 20);
            pb0 = *(const float4*)(Bp + k0 + 16); pb1 = *(const float4*)(Bp + k0 + 20);
        }
        COMPUTE_TILE(As[buf], Bs[buf]);
        if (more) {
            const int nb = buf ^ 1;
            STS8(As, nb, pa0, pa1);
            STS8(Bs, nb, pb0, pb1);
        }
        __syncthreads();
        buf ^= 1;
    }

    const int ac2 = (lane & 3) * 2;
#pragma unroll
    for (int nt = 0; nt < 4; nt++) {
        const int col = bn + wn + nt * 8 + ac2;
#pragma unroll
        for (int mt = 0; mt < 4; mt++) {
            const int r0 = bm + wm + mt * 16 + ar;
            *(float2*)&C[(size_t)r0 * Sc + col] =
                make_float2(acc[mt][nt][0] * SCALE, acc[mt][nt][1] * SCALE);
            *(float2*)&C[(size_t)(r0 + 8) * Sc + col] =
                make_float2(acc[mt][nt][2] * SCALE, acc[mt][nt][3] * SCALE);
        }
    }
}

// ---------------- causal row softmax, float4 over valid groups ----------------
__global__ __launch_bounds__(256) void softmax_kernel(const float* __restrict__ amask)
{
    const int row = blockIdx.x;
    const int q = row & (Sc - 1);
    const int b = row >> 15;               // / (NHc*Sc)
    float* ap = g_attn + (size_t)row * Sc;
    const float* mp = amask + (size_t)b * Sc;

    const int tid = threadIdx.x, lane = tid & 31, w = tid >> 5;
    __shared__ float sred[8];

    const int nv = (q >> 2) + 1;           // float4 groups covering [0, q]
    float4 x[2];
    float lm = -3.4e38f;
#pragma unroll
    for (int it = 0; it < 2; it++) {
        const int g = tid + it * 256;
        if (g < nv) {
            float4 v = *(const float4*)(ap + g * 4);
            float4 m = *(const float4*)(mp + g * 4);
            const int k = g * 4;
            v.x = (k + 0 <= q) ? v.x + m.x : -3.4e38f;
            v.y = (k + 1 <= q) ? v.y + m.y : -3.4e38f;
            v.z = (k + 2 <= q) ? v.z + m.z : -3.4e38f;
            v.w = (k + 3 <= q) ? v.w + m.w : -3.4e38f;
            x[it] = v;
            lm = fmaxf(lm, fmaxf(fmaxf(v.x, v.y), fmaxf(v.z, v.w)));
        } else {
            x[it] = make_float4(-3.4e38f, -3.4e38f, -3.4e38f, -3.4e38f);
        }
    }
#pragma unroll
    for (int o = 16; o > 0; o >>= 1) lm = fmaxf(lm, __shfl_xor_sync(0xffffffffu, lm, o));
    if (lane == 0) sred[w] = lm;
    __syncthreads();
    float m = sred[0];
#pragma unroll
    for (int i = 1; i < 8; i++) m = fmaxf(m, sred[i]);
    __syncthreads();

    float ls = 0.f;
#pragma unroll
    for (int it = 0; it < 2; it++) {
        const int g = tid + it * 256;
        if (g < nv) {
            float4 v = x[it];
            v.x = __expf(v.x - m); v.y = __expf(v.y - m);
            v.z = __expf(v.z - m); v.w = __expf(v.w - m);
            x[it] = v;
            ls += v.x + v.y + v.z + v.w;
        }
    }
#pragma unroll
    for (int o = 16; o > 0; o >>= 1) ls += __shfl_xor_sync(0xffffffffu, ls, o);
    if (lane == 0) sred[w] = ls;
    __syncthreads();
    float s = 0.f;
#pragma unroll
    for (int i = 0; i < 8; i++) s += sred[i];
    const float inv = 1.0f / s;

#pragma unroll
    for (int it = 0; it < 2; it++) {
        const int g = tid + it * 256;
        if (g < nv) {
            float4 v = x[it];
            *(float4*)(ap + g * 4) =
                make_float4(v.x * inv, v.y * inv, v.z * inv, v.w * inv);
        }
    }
}

// ---------------- column-sum partials per q-chunk (deterministic) ----------------
__global__ void colpart_kernel()
{
    const int k = blockIdx.x * 256 + threadIdx.x;
    const int h = blockIdx.y;
    const int z = blockIdx.z;
    const int qlo = z * 256, qhi = qlo + 256;
    const int qs = (k > qlo) ? k : qlo;
    const bool rz = (z == NQCH - 1);
    float s = 0.f, r = 0.f;
    for (int b = 0; b < Bc; b++) {
        const float* ap = g_attn + ((size_t)(b * NHc + h)) * Sc * Sc;
        for (int q = qs; q < qhi; q++) {
            float a = ap[(size_t)q * Sc + k];
            s += a;
            if (rz && q >= Sc - MBc) r += a;
        }
    }
    g_colpart[((size_t)z * NHc + h) * Sc + k] = s;
    if (rz) g_ratio[h * Sc + k] = r;
}

__global__ void colsumfin_kernel()
{
    const int k = blockIdx.x * 256 + threadIdx.x;
    const int h = blockIdx.y;
    float s = 0.f;
#pragma unroll
    for (int z = 0; z < NQCH; z++) s += g_colpart[((size_t)z * NHc + h) * Sc + k];
    g_colsum[h * Sc + k] = s;
}

// ---------------- top-k per head (jax tie-break: lowest index) ----------------
__global__ __launch_bounds__(256) void topk_kernel()
{
    const int h = blockIdx.x, tid = threadIdx.x;
    __shared__ float tv[NCAND];
    __shared__ float rv[256];
    __shared__ int   ri[256];

    for (int i = tid; i < NCAND; i += 256) tv[i] = g_colsum[h * Sc + SBc + i];
    __syncthreads();

    for (int r = 0; r < TKc; r++) {
        float bv = -1e30f; int bi = NCAND;
        for (int i = tid; i < NCAND; i += 256) {
            float v = tv[i];
            if (v > bv) { bv = v; bi = i; }
        }
        rv[tid] = bv; ri[tid] = bi;
        __syncthreads();
        for (int st = 128; st > 0; st >>= 1) {
            if (tid < st) {
                if (rv[tid + st] > rv[tid] ||
                    (rv[tid + st] == rv[tid] && ri[tid + st] < ri[tid])) {
                    rv[tid] = rv[tid + st]; ri[tid] = ri[tid + st];
                }
            }
            __syncthreads();
        }
        if (tid == 0) {
            const int gi = ri[0] + SBc;
            g_topidx[h * TKc + r] = gi;
            g_topval[h * TKc + r] = g_ratio[h * Sc + gi] * (1.0f / MBc);
            tv[ri[0]] = -1e30f;
        }
        __syncthreads();
    }
}

// ---------------- v[b,h,SB,:] = sum_j v[b,h,idx_j,:] * val_j ----------------
__global__ void vupdate_kernel()
{
    const int bh = blockIdx.x;
    const int h  = bh % NHc;
    const int d  = threadIdx.x;
    float* vp = g_v + (size_t)bh * Sc * HDc;
    float acc = 0.f;
#pragma unroll
    for (int j = 0; j < TKc; j++)
        acc += vp[(size_t)g_topidx[h * TKc + j] * HDc + d] * g_topval[h * TKc + j];
    vp[(size_t)SBc * HDc + d] = acc;
}

// ================= out = attn @ v (TF32, causal, dbuf), scatter ==============
__global__ __launch_bounds__(256) void attnv_tc()
{
    __shared__ unsigned As[2][16][APAD]; // [k][m]
    __shared__ unsigned Vs[2][128][20];  // [n][k]

    const int tid = threadIdx.x, lane = tid & 31, w = tid >> 5;
    const int bh = blockIdx.y;
    const int bm = blockIdx.x * 128;
    const int wm = (w >> 2) * 64, wn = (w & 3) * 32;
    const int ar = lane >> 2, ak = lane & 3;

    const float* attn = g_attn + (size_t)bh * Sc * Sc;
    const float* vp   = g_v    + (size_t)bh * Sc * HDc;

    const int lrow = tid & 127, lkh = (tid >> 7) * 8;
    const int q_l = bm + lrow;
    const float* arow = attn + (size_t)q_l * Sc;
    const int vk = tid & 15, vn = (tid >> 4) * 8;

    float acc[4][4][4];
#pragma unroll
    for (int mt = 0; mt < 4; mt++)
#pragma unroll
        for (int nt = 0; nt < 4; nt++)
#pragma unroll
            for (int i = 0; i < 4; i++) acc[mt][nt][i] = 0.f;

    const int kend = bm + 128;

#define STS_A_MASKED(BUFI, V0, V1, KB)                                        \
    As[BUFI][lkh+0][lrow] = ((KB)+0 <= q_l) ? f2t(V0.x) : 0u;                 \
    As[BUFI][lkh+1][lrow] = ((KB)+1 <= q_l) ? f2t(V0.y) : 0u;                 \
    As[BUFI][lkh+2][lrow] = ((KB)+2 <= q_l) ? f2t(V0.z) : 0u;                 \
    As[BUFI][lkh+3][lrow] = ((KB)+3 <= q_l) ? f2t(V0.w) : 0u;                 \
    As[BUFI][lkh+4][lrow] = ((KB)+4 <= q_l) ? f2t(V1.x) : 0u;                 \
    As[BUFI][lkh+5][lrow] = ((KB)+5 <= q_l) ? f2t(V1.y) : 0u;                 \
    As[BUFI][lkh+6][lrow] = ((KB)+6 <= q_l) ? f2t(V1.z) : 0u;                 \
    As[BUFI][lkh+7][lrow] = ((KB)+7 <= q_l) ? f2t(V1.w) : 0u;

#define STS_V(BUFI, V0, V1)                                                   \
    Vs[BUFI][vn+0][vk]=f2t(V0.x); Vs[BUFI][vn+1][vk]=f2t(V0.y);               \
    Vs[BUFI][vn+2][vk]=f2t(V0.z); Vs[BUFI][vn+3][vk]=f2t(V0.w);               \
    Vs[BUFI][vn+4][vk]=f2t(V1.x); Vs[BUFI][vn+5][vk]=f2t(V1.y);               \
    Vs[BUFI][vn+6][vk]=f2t(V1.z); Vs[BUFI][vn+7][vk]=f2t(V1.w);

    // prologue: tile k0 = 0
    {
        float4 a0v = *(const float4*)(arow + lkh);
        float4 a1v = *(const float4*)(arow + lkh + 4);
        STS_A_MASKED(0, a0v, a1v, lkh);
        const float* vr = vp + (size_t)vk * HDc + vn;
        float4 v0 = *(const float4*)vr, v1 = *(const float4*)(vr + 4);
        STS_V(0, v0, v1);
    }
    __syncthreads();

    int buf = 0;
    for (int k0 = 0; k0 < kend; k0 += 16) {
        const bool more = (k0 + 16 < kend);
        float4 a0v, a1v, v0, v1;
        if (more) {
            a0v = *(const float4*)(arow + k0 + 16 + lkh);
            a1v = *(const float4*)(arow + k0 + 20 + lkh);
            const float* vr = vp + (size_t)(k0 + 16 + vk) * HDc + vn;
            v0 = *(const float4*)vr; v1 = *(const float4*)(vr + 4);
        }

#pragma unroll
        for (int ks = 0; ks < 16; ks += 8) {
            unsigned afr[4][4], bfr[4][2];
#pragma unroll
            for (int mt = 0; mt < 4; mt++) {
                const int m0 = wm + mt * 16 + ar;
                afr[mt][0] = As[buf][ks+ak][m0];
                afr[mt][1] = As[buf][ks+ak][m0+8];
                afr[mt][2] = As[buf][ks+4+ak][m0];
                afr[mt][3] = As[buf][ks+4+ak][m0+8];
            }
#pragma unroll
            for (int nt = 0; nt < 4; nt++) {
                const int n0 = wn + nt * 8 + ar;
                bfr[nt][0] = Vs[buf][n0][ks+ak];
                bfr[nt][1] = Vs[buf][n0][ks+4+ak];
            }
#pragma unroll
            for (int mt = 0; mt < 4; mt++)
#pragma unroll
                for (int nt = 0; nt < 4; nt++) mma8(acc[mt][nt], afr[mt], bfr[nt]);
        }

        if (more) {
            const int nb = buf ^ 1;
            const int kb2 = k0 + 16 + lkh;
            STS_A_MASKED(nb, a0v, a1v, kb2);
            STS_V(nb, v0, v1);
        }
        __syncthreads();
        buf ^= 1;
    }

    const int b = bh >> 4, h = bh & 15;
    const int ac2 = (lane & 3) * 2;
#pragma unroll
    for (int nt = 0; nt < 4; nt++) {
        const int col = h * HDc + wn + nt * 8 + ac2;
#pragma unroll
        for (int mt = 0; mt < 4; mt++) {
            const int q = bm + wm + mt * 16 + ar;
            *(float2*)&g_outh[((size_t)(b * Sc + q)) * HIDc + col] =
                make_float2(acc[mt][nt][0], acc[mt][nt][1]);
            *(float2*)&g_outh[((size_t)(b * Sc + q + 8)) * HIDc + col] =
                make_float2(acc[mt][nt][2], acc[mt][nt][3]);
        }
    }
#undef STS_A_MASKED
#undef STS_V
}

// ---------------- launch ----------------
extern "C" void kernel_launch(void* const* d_in, const int* in_sizes, int n_in,
                              void* d_out, int out_size)
{
    (void)in_sizes; (void)n_in; (void)out_size;
    const float* hs    = (const float*)d_in[0];
    const float* amask = (const float*)d_in[1];
    const int*   pos   = (const int*)  d_in[2];
    const float* Wqkv  = (const float*)d_in[3];
    const float* bqkv  = (const float*)d_in[4];
    const float* Wd    = (const float*)d_in[5];
    const float* bd    = (const float*)d_in[6];
    float* out = (float*)d_out;

    void *p_q = nullptr, *p_k = nullptr, *p_v = nullptr, *p_outh = nullptr;
    cudaGetSymbolAddress(&p_q, g_q);
    cudaGetSymbolAddress(&p_k, g_k);
    cudaGetSymbolAddress(&p_v, g_v);
    cudaGetSymbolAddress(&p_outh, g_outh);

    cudaFuncSetAttribute(qkv_gemm_tc,
                         cudaFuncAttributeMaxDynamicSharedMemorySize, SMEMDYN);
    cudaFuncSetAttribute(gemm_tn_tc256,
                         cudaFuncAttributeMaxDynamicSharedMemorySize, SMEMDYN);

    // 1. QKV projection + per-head scatter (TF32, 128x256, dbuf)
    qkv_gemm_tc<<<dim3(3 * HIDc / 256, (Bc * Sc) / 128), 256, SMEMDYN>>>(
        hs, Wqkv, bqkv, (float*)p_q, (float*)p_k, (float*)p_v);

    // 2. RoPE in place on rotary dims
    rope_inplace<<<dim3(Sc, NHc, Bc), 64>>>(pos);

    // 3. scaled QK^T (causal tiles, TF32, dbuf)
    scores_tc<<<dim3(Sc / 128, Sc / 128, Bc * NHc), 256>>>();

    // 4. row softmax (vectorized, causal groups only)
    softmax_kernel<<<Bc * NHc * Sc, 256>>>(amask);

    // 5a/5b. column statistics: per-chunk partials + fixed-order sum
    colpart_kernel<<<dim3(Sc / 256, NHc, NQCH), 256>>>();
    colsumfin_kernel<<<dim3(Sc / 256, NHc), 256>>>();

    // 6. per-head top-16
    topk_kernel<<<NHc, 256>>>();

    // 7. merged row write into v
    vupdate_kernel<<<Bc * NHc, HDc>>>();

    // 8. attn @ v (TF32, dbuf)
    attnv_tc<<<dim3(Sc / 128, Bc * NHc), 256>>>();

    // 9. dense projection (TF32, 128x256, dbuf)
    gemm_tn_tc256<<<dim3(HIDc / 256, (Bc * Sc) / 128), 256, SMEMDYN>>>(
        (const float*)p_outh, Wd, bd, out, Bc * Sc, HIDc, HIDc);
}